// round 3
// baseline (speedup 1.0000x reference)
#include <cuda_runtime.h>
#include <math.h>

#define BB 4
#define CC 3
#define HH 384
#define WW 384
#define HWs (HH*WW)
#define NBC (BB*CC)
#define NTOT (NBC*HWs)
#define NBE (CC*HWs)
#define IRK 16
#define NPART 432

// ------------ static device scratch (no allocations allowed) ------------
__device__ float d_b[NTOT];
__device__ float d_r[NTOT];
__device__ float d_p[NTOT];
__device__ float d_Ap[NTOT];
__device__ float d_t1[NTOT];
__device__ float d_t2[NTOT];
__device__ float d_wreg[(size_t)IRK * NTOT];
__device__ float d_part[BB * 512];
__device__ float d_scal[16]; // [0..3]=rs, [4..7]=alpha, [8..11]=beta, [12..15]=active

__device__ __forceinline__ float warpRed(float v) {
#pragma unroll
    for (int o = 16; o > 0; o >>= 1) v += __shfl_down_sync(0xffffffffu, v, o);
    return v;
}

// ---------------- 11x11 per-batch correlation, SAME, zero pad ----------------
// block (32,8): 32x32 output tile, 4 rows per thread. grid (12,12,12)
__global__ __launch_bounds__(256)
void corr11_k(const float* __restrict__ in, float* __restrict__ out,
              const float* __restrict__ kern, int flip)
{
    __shared__ float tile[42 * 42];
    __shared__ float sk[121];
    const int bc = blockIdx.z;
    const int bat = bc / CC;
    const float* ip = in + (size_t)bc * HWs;
    const int tid = threadIdx.y * 32 + threadIdx.x;
    if (tid < 121) sk[tid] = kern[bat * 121 + (flip ? 120 - tid : tid)];
    const int X0 = blockIdx.x * 32, Y0 = blockIdx.y * 32;
    for (int k = tid; k < 42 * 42; k += 256) {
        int sy = k / 42, sx = k % 42;
        int gy = Y0 - 5 + sy, gx = X0 - 5 + sx;
        tile[k] = (gy >= 0 && gy < HH && gx >= 0 && gx < WW) ? ip[gy * WW + gx] : 0.f;
    }
    __syncthreads();
    float a0 = 0, a1 = 0, a2 = 0, a3 = 0;
    const int ry = threadIdx.y * 4, tx = threadIdx.x;
#pragma unroll
    for (int v = 0; v < 11; v++) {
        float kc[11];
#pragma unroll
        for (int u = 0; u < 11; u++) kc[u] = sk[u * 11 + v];
#pragma unroll
        for (int rr = 0; rr < 14; rr++) {
            float val = tile[(ry + rr) * 42 + tx + v];
            if (rr <= 10)           a0 += val * kc[rr];
            if (rr >= 1 && rr <= 11) a1 += val * kc[rr - 1];
            if (rr >= 2 && rr <= 12) a2 += val * kc[rr - 2];
            if (rr >= 3)            a3 += val * kc[rr - 3];
        }
    }
    float* op = out + (size_t)bc * HWs + (size_t)(Y0 + ry) * WW + X0 + tx;
    op[0] = a0; op[WW] = a1; op[2 * WW] = a2; op[3 * WW] = a3;
}

// -------- fused out = sum_i K_i^T ( kw_i * wreg_i * (K_i v) ), exact SAME-pad --------
// block (36,8) = 288 threads; 32x32 output tile. grid (12,12,12)
__global__ __launch_bounds__(288)
void ata_k(const float* __restrict__ in, float* __restrict__ out,
           const float* __restrict__ ks, const float* __restrict__ kw,
           const float* __restrict__ wreg, int I, int accum)
{
    __shared__ float vt[40 * 40];      // input with ±4 halo
    __shared__ float tt[36 * 36];      // stage-1 t_i with ±2 halo
    __shared__ float sk[IRK * 25];
    __shared__ float skw[IRK];
    const int bc = blockIdx.z;
    const float* ip = in + (size_t)bc * HWs;
    const int tid = threadIdx.y * 36 + threadIdx.x;
    for (int k = tid; k < I * 25; k += 288) sk[k] = ks[k];
    if (tid < I) skw[tid] = kw[tid];
    const int X0 = blockIdx.x * 32, Y0 = blockIdx.y * 32;
    for (int k = tid; k < 40 * 40; k += 288) {
        int sy = k / 40, sx = k % 40;
        int gy = Y0 - 4 + sy, gx = X0 - 4 + sx;
        vt[k] = (gy >= 0 && gy < HH && gx >= 0 && gx < WW) ? ip[gy * WW + gx] : 0.f;
    }
    __syncthreads();
    const int tx = threadIdx.x;   // 0..35
    const int ty = threadIdx.y;   // 0..7
    const int syb = ty * 5;
    float a0 = 0, a1 = 0, a2 = 0, a3 = 0;
    for (int i = 0; i < I; i++) {
        float kr[25];
#pragma unroll
        for (int k = 0; k < 25; k++) kr[k] = sk[i * 25 + k];
        const float kwv = skw[i];
        __syncthreads(); // previous iteration's tt reads complete
        // ---- stage 1: t_i on the 36x36 halo region ----
        float tv0 = 0, tv1 = 0, tv2 = 0, tv3 = 0, tv4 = 0;
#pragma unroll
        for (int v = 0; v < 5; v++) {
#pragma unroll
            for (int rr = 0; rr < 9; rr++) {
                float val = vt[(syb + rr) * 40 + tx + v];
                int u;
                u = rr;     if (u <= 4)            tv0 += val * kr[u * 5 + v];
                u = rr - 1; if (u >= 0 && u <= 4)  tv1 += val * kr[u * 5 + v];
                u = rr - 2; if (u >= 0 && u <= 4)  tv2 += val * kr[u * 5 + v];
                u = rr - 3; if (u >= 0 && u <= 4)  tv3 += val * kr[u * 5 + v];
                u = rr - 4; if (u >= 0)            tv4 += val * kr[u * 5 + v];
            }
        }
        {
            float tvs[5] = {tv0, tv1, tv2, tv3, tv4};
#pragma unroll
            for (int k = 0; k < 5; k++) {
                int sy = syb + k;
                if (sy < 36) {
                    int gy = Y0 - 2 + sy, gx = X0 - 2 + tx;
                    float o = 0.f;
                    if (gy >= 0 && gy < HH && gx >= 0 && gx < WW) {
                        float w = kwv;
                        if (wreg) w *= wreg[((size_t)(bc * IRK + i)) * HWs + (size_t)gy * WW + gx];
                        o = tvs[k] * w;
                    }
                    tt[sy * 36 + tx] = o;
                }
            }
        }
        __syncthreads();
        // ---- stage 2: adjoint into per-thread accumulators ----
        if (tx < 32) {
            const int ry = ty * 4;
#pragma unroll
            for (int v = 0; v < 5; v++) {
                int col = tx + 4 - v;
#pragma unroll
                for (int rr = 0; rr < 8; rr++) {
                    float val = tt[(ry + rr) * 36 + col];
                    int u;
                    u = 4 - rr; if (u >= 0 && u <= 4) a0 += val * kr[u * 5 + v];
                    u = 5 - rr; if (u >= 0 && u <= 4) a1 += val * kr[u * 5 + v];
                    u = 6 - rr; if (u >= 0 && u <= 4) a2 += val * kr[u * 5 + v];
                    u = 7 - rr; if (u >= 0 && u <= 4) a3 += val * kr[u * 5 + v];
                }
            }
        }
    }
    if (tx < 32) {
        const int ry = ty * 4;
        float accs[4] = {a0, a1, a2, a3};
#pragma unroll
        for (int k2 = 0; k2 < 4; k2++) {
            size_t o = (size_t)bc * HWs + (size_t)(Y0 + ry + k2) * WW + X0 + tx;
            if (accum) out[o] += accs[k2]; else out[o] = accs[k2];
        }
    }
}

// -------- GMM reweighting: w_reg_j(p) from g_j = corr5(x, rks_j) --------
__global__ __launch_bounds__(256)
void gmm_k(const float* __restrict__ x, const float* __restrict__ rks,
           const float* __restrict__ gw, const float* __restrict__ giv)
{
    __shared__ float tile[36 * 36];
    __shared__ float sk[IRK * 25];
    const int bc = blockIdx.z;
    const float* ip = x + (size_t)bc * HWs;
    const int tid = threadIdx.y * 32 + threadIdx.x;
    for (int k = tid; k < IRK * 25; k += 256) sk[k] = rks[k];
    const int X0 = blockIdx.x * 32, Y0 = blockIdx.y * 32;
    for (int k = tid; k < 36 * 36; k += 256) {
        int sy = k / 36, sx = k % 36;
        int gy = Y0 - 2 + sy, gx = X0 - 2 + sx;
        tile[k] = (gy >= 0 && gy < HH && gx >= 0 && gx < WW) ? ip[gy * WW + gx] : 0.f;
    }
    __syncthreads();
    const int ry = threadIdx.y * 4, tx = threadIdx.x;
    for (int j = 0; j < IRK; j++) {
        float kr[25];
#pragma unroll
        for (int k = 0; k < 25; k++) kr[k] = sk[j * 25 + k];
        float g0 = 0, g1 = 0, g2 = 0, g3 = 0;
#pragma unroll
        for (int v = 0; v < 5; v++) {
#pragma unroll
            for (int rr = 0; rr < 8; rr++) {
                float val = tile[(ry + rr) * 36 + tx + v];
                int u;
                u = rr;     if (u <= 4)           g0 += val * kr[u * 5 + v];
                u = rr - 1; if (u >= 0 && u <= 4) g1 += val * kr[u * 5 + v];
                u = rr - 2; if (u >= 0 && u <= 4) g2 += val * kr[u * 5 + v];
                u = rr - 3; if (u >= 0)           g3 += val * kr[u * 5 + v];
            }
        }
        float iv0 = giv[0 * IRK + j], iv1 = giv[1 * IRK + j], iv2 = giv[2 * IRK + j];
        float c0 = gw[0 * IRK + j] * sqrtf(iv0);
        float c1 = gw[1 * IRK + j] * sqrtf(iv1);
        float c2 = gw[2 * IRK + j] * sqrtf(iv2);
        float gs[4] = {g0, g1, g2, g3};
#pragma unroll
        for (int k2 = 0; k2 < 4; k2++) {
            float gv = gs[k2];
            float p0 = c0 * expf(-0.5f * iv0 * gv * gv);
            float p1 = c1 * expf(-0.5f * iv1 * gv * gv);
            float p2 = c2 * expf(-0.5f * iv2 * gv * gv);
            float num = p0 * iv0 + p1 * iv1 + p2 * iv2;
            float den = p0 + p1 + p2 + 1e-12f;
            d_wreg[((size_t)(bc * IRK + j)) * HWs + (size_t)(Y0 + ry + k2) * WW + X0 + tx] = num / den;
        }
    }
}

// ---------------- CG vector/reduction kernels (deterministic) ----------------
__device__ __forceinline__ void blockStore256(float s, int b, int bx) {
    __shared__ float sm[8];
    s = warpRed(s);
    if ((threadIdx.x & 31) == 0) sm[threadIdx.x >> 5] = s;
    __syncthreads();
    if (threadIdx.x == 0) {
        float v = 0;
#pragma unroll
        for (int i = 0; i < 8; i++) v += sm[i];
        d_part[b * 512 + bx] = v;
    }
}

// grid (NPART, BB), block 256; each block covers 1024 elements
__global__ __launch_bounds__(256)
void resid_init_k() {
    const int b = blockIdx.y;
    size_t base = (size_t)b * NBE + (size_t)blockIdx.x * 1024 + threadIdx.x;
    float s = 0;
#pragma unroll
    for (int k = 0; k < 4; k++) {
        size_t idx = base + (size_t)k * 256;
        float rv = d_b[idx] - d_Ap[idx];
        d_r[idx] = rv; d_p[idx] = rv;
        s += rv * rv;
    }
    blockStore256(s, b, blockIdx.x);
}

__global__ __launch_bounds__(256)
void dot_k() {
    const int b = blockIdx.y;
    size_t base = (size_t)b * NBE + (size_t)blockIdx.x * 1024 + threadIdx.x;
    float s = 0;
#pragma unroll
    for (int k = 0; k < 4; k++) {
        size_t idx = base + (size_t)k * 256;
        s += d_p[idx] * d_Ap[idx];
    }
    blockStore256(s, b, blockIdx.x);
}

__global__ __launch_bounds__(256)
void update_xr_k(float* __restrict__ x) {
    const int b = blockIdx.y;
    const float alpha = d_scal[4 + b];
    size_t base = (size_t)b * NBE + (size_t)blockIdx.x * 1024 + threadIdx.x;
    float s = 0;
#pragma unroll
    for (int k = 0; k < 4; k++) {
        size_t idx = base + (size_t)k * 256;
        x[idx] += alpha * d_p[idx];
        float rv = d_r[idx] - alpha * d_Ap[idx];
        d_r[idx] = rv;
        s += rv * rv;
    }
    blockStore256(s, b, blockIdx.x);
}

__global__ __launch_bounds__(256)
void update_p_k() {
    const int b = blockIdx.y;
    const float beta = d_scal[8 + b];
    const int active = d_scal[12 + b] != 0.f;
    size_t base = (size_t)b * NBE + (size_t)blockIdx.x * 1024 + threadIdx.x;
#pragma unroll
    for (int k = 0; k < 4; k++) {
        size_t idx = base + (size_t)k * 256;
        if (active) d_p[idx] = d_r[idx] + beta * d_p[idx];
    }
}

// ---------------- scalar kernels: one block per batch ----------------
__device__ __forceinline__ float reducePart(int b) {
    int t = threadIdx.x;
    float s = 0;
    for (int i = t; i < NPART; i += 256) s += d_part[b * 512 + i];
    __shared__ float sm[8];
    s = warpRed(s);
    if ((t & 31) == 0) sm[t >> 5] = s;
    __syncthreads();
    float v = 0;
    if (t == 0) {
#pragma unroll
        for (int i = 0; i < 8; i++) v += sm[i];
    }
    return v; // valid only on thread 0
}

__global__ void scal_rs_k() {
    int b = blockIdx.x;
    float v = reducePart(b);
    if (threadIdx.x == 0) d_scal[b] = v;
}

__global__ void scal_alpha_k() {
    int b = blockIdx.x;
    float pAp = reducePart(b);
    if (threadIdx.x == 0) {
        float rs = d_scal[b];
        int active = sqrtf(rs) > 1e-6f;
        d_scal[12 + b] = active ? 1.f : 0.f;
        d_scal[4 + b] = active ? rs / fmaxf(pAp, 1e-12f) : 0.f;
    }
}

__global__ void scal_beta_k() {
    int b = blockIdx.x;
    float rs_new = reducePart(b);
    if (threadIdx.x == 0) {
        float rs = d_scal[b];
        int active = d_scal[12 + b] != 0.f;
        d_scal[8 + b] = active ? rs_new / fmaxf(rs, 1e-12f) : 0.f;
        d_scal[b] = active ? rs_new : rs;
    }
}

// ---------------- host orchestration ----------------
static void Aop(const float* v, float* out, const float* kern,
                const float* dks, const float* dkw,
                const float* rks, const float* rkw,
                const float* wreg)
{
    dim3 g(12, 12, NBC);
    float *t1, *t2;
    cudaGetSymbolAddress((void**)&t1, d_t1);
    cudaGetSymbolAddress((void**)&t2, d_t2);
    corr11_k<<<g, dim3(32, 8)>>>(v, t1, kern, 0);
    ata_k<<<g, dim3(36, 8)>>>(t1, t2, dks, dkw, nullptr, 8, 0);
    corr11_k<<<g, dim3(32, 8)>>>(t2, out, kern, 1);
    ata_k<<<g, dim3(36, 8)>>>(v, out, rks, rkw, wreg, IRK, 1);
}

extern "C" void kernel_launch(void* const* d_in, const int* in_sizes, int n_in,
                              void* d_out, int out_size)
{
    const float* blurred = (const float*)d_in[0];
    const float* kern    = (const float*)d_in[1];
    const float* dkw     = (const float*)d_in[2];
    const float* dks     = (const float*)d_in[3];
    const float* rkw     = (const float*)d_in[4];
    const float* rks     = (const float*)d_in[5];
    const float* gmmw    = (const float*)d_in[6];
    const float* gmmiv   = (const float*)d_in[7];
    float* x = (float*)d_out;

    float *pb, *pAp, *pt1, *pwreg, *pp;
    cudaGetSymbolAddress((void**)&pb, d_b);
    cudaGetSymbolAddress((void**)&pAp, d_Ap);
    cudaGetSymbolAddress((void**)&pt1, d_t1);
    cudaGetSymbolAddress((void**)&pwreg, d_wreg);
    cudaGetSymbolAddress((void**)&pp, d_p);

    const int n_irls = 2, n_cg = 8;
    dim3 g(12, 12, NBC);
    dim3 gr(NPART, BB);

    // x = blurred
    cudaMemcpyAsync(x, blurred, (size_t)NTOT * sizeof(float),
                    cudaMemcpyDeviceToDevice, 0);

    // b = K^T D^T W_d D blurred   (IRLS-invariant since reg_targets == 0)
    ata_k<<<g, dim3(36, 8)>>>(blurred, pt1, dks, dkw, nullptr, 8, 0);
    corr11_k<<<g, dim3(32, 8)>>>(pt1, pb, kern, 1);

    for (int it = 0; it < n_irls; it++) {
        const float* wreg = (it == 0) ? nullptr : pwreg;
        if (it == 1)
            gmm_k<<<g, dim3(32, 8)>>>(x, rks, gmmw, gmmiv);

        // r = b - A x; p = r; rs = <r,r>
        Aop(x, pAp, kern, dks, dkw, rks, rkw, wreg);
        resid_init_k<<<gr, 256>>>();
        scal_rs_k<<<BB, 256>>>();

        for (int s = 0; s < n_cg; s++) {
            Aop(pp, pAp, kern, dks, dkw, rks, rkw, wreg);
            dot_k<<<gr, 256>>>();
            scal_alpha_k<<<BB, 256>>>();
            update_xr_k<<<gr, 256>>>(x);
            scal_beta_k<<<BB, 256>>>();
            update_p_k<<<gr, 256>>>();
        }
    }
}

// round 4
// speedup vs baseline: 1.6682x; 1.6682x over previous
#include <cuda_runtime.h>
#include <math.h>

#define BB 4
#define CC 3
#define HH 384
#define WW 384
#define HWs (HH*WW)
#define NBC (BB*CC)
#define NTOT (NBC*HWs)
#define NBE (CC*HWs)
#define IRK 16
#define NPART 432

// ------------ static device scratch ------------
__device__ float d_b[NTOT];
__device__ float d_r[NTOT];
__device__ float d_p[NTOT];
__device__ float d_Ap[NTOT];
__device__ float d_t1[NTOT];
__device__ float d_t2[NTOT];
__device__ float d_wreg[(size_t)IRK * NTOT];
__device__ float d_part[BB * 512];
__device__ float d_scal[16];
__device__ float d_S[162]; // [0..80]=S_data, [81..161]=S_reg

__device__ __forceinline__ float warpRed(float v) {
#pragma unroll
    for (int o = 16; o > 0; o >>= 1) v += __shfl_down_sync(0xffffffffu, v, o);
    return v;
}

// ------- build composed 9x9 kernels S(d) = sum_i kw_i sum_e k_i(e) k_i(e+d) -------
__global__ void autocorr_k(const float* __restrict__ dks, const float* __restrict__ dkw,
                           const float* __restrict__ rks, const float* __restrict__ rkw)
{
    int tid = threadIdx.x;
    if (tid < 162) {
        int which = tid / 81, t = tid % 81;
        const float* ks = which ? rks : dks;
        const float* kw = which ? rkw : dkw;
        int I = which ? 16 : 8;
        int dy = t / 9 - 4, dx = t % 9 - 4;
        float s = 0.f;
        for (int i = 0; i < I; i++) {
            float w = kw[i];
            for (int u = 0; u < 5; u++)
                for (int v = 0; v < 5; v++) {
                    int u2 = u + dy, v2 = v + dx;
                    if (u2 >= 0 && u2 < 5 && v2 >= 0 && v2 < 5)
                        s += w * ks[i * 25 + u * 5 + v] * ks[i * 25 + u2 * 5 + v2];
                }
        }
        d_S[which * 81 + t] = s;
    }
}

// ---------------- 11x11 per-batch correlation, SAME, zero pad ----------------
// block (16,8)=128 threads: each thread 2 cols x 4 rows of a 32x32 tile. grid (12,12,12)
__global__ __launch_bounds__(128)
void corr11_k(const float* __restrict__ in, float* __restrict__ out,
              const float* __restrict__ kern, int flip)
{
    __shared__ float tile[42 * 42];
    __shared__ float sk[121];
    const int bc = blockIdx.z;
    const int bat = bc / CC;
    const float* ip = in + (size_t)bc * HWs;
    const int tid = threadIdx.y * 16 + threadIdx.x;
    if (tid < 121) sk[tid] = kern[bat * 121 + (flip ? 120 - tid : tid)];
    const int X0 = blockIdx.x * 32, Y0 = blockIdx.y * 32;
    for (int k = tid; k < 42 * 42; k += 128) {
        int sy = k / 42, sx = k % 42;
        int gy = Y0 - 5 + sy, gx = X0 - 5 + sx;
        tile[k] = (gy >= 0 && gy < HH && gx >= 0 && gx < WW) ? ip[gy * WW + gx] : 0.f;
    }
    __syncthreads();
    const int ry = threadIdx.y * 4;
    const int cx = threadIdx.x * 2;
    float acc0[4] = {0, 0, 0, 0}, acc1[4] = {0, 0, 0, 0};
    float kp[11];
#pragma unroll
    for (int a = 0; a < 12; a++) {
        float kc[11];
        if (a < 11) {
#pragma unroll
            for (int u = 0; u < 11; u++) kc[u] = sk[u * 11 + a];
        }
#pragma unroll
        for (int rr = 0; rr < 14; rr++) {
            float val = tile[(ry + rr) * 42 + cx + a];
#pragma unroll
            for (int k = 0; k < 4; k++) {
                int u = rr - k;
                if (u >= 0 && u <= 10) {
                    if (a < 11) acc0[k] += val * kc[u];
                    if (a >= 1) acc1[k] += val * kp[u];
                }
            }
        }
        if (a < 11) {
#pragma unroll
            for (int u = 0; u < 11; u++) kp[u] = kc[u];
        }
    }
    float* op = out + (size_t)bc * HWs + (size_t)(Y0 + ry) * WW + X0 + cx;
#pragma unroll
    for (int k = 0; k < 4; k++) {
        op[k * WW] = acc0[k];
        op[k * WW + 1] = acc1[k];
    }
}

// ------- 9x9 composed conv: interior pixels only (dist>=2). optional accumulate -------
// block (16,8)=128 threads, 32x32 tile, grid (12,12,12)
__global__ __launch_bounds__(128)
void conv9_k(const float* __restrict__ in, float* __restrict__ out,
             const float* __restrict__ S, int accum)
{
    __shared__ float tile[40 * 40];
    __shared__ float sk[81];
    const int bc = blockIdx.z;
    const float* ip = in + (size_t)bc * HWs;
    const int tid = threadIdx.y * 16 + threadIdx.x;
    if (tid < 81) sk[tid] = S[tid];
    const int X0 = blockIdx.x * 32, Y0 = blockIdx.y * 32;
    for (int k = tid; k < 40 * 40; k += 128) {
        int sy = k / 40, sx = k % 40;
        int gy = Y0 - 4 + sy, gx = X0 - 4 + sx;
        tile[k] = (gy >= 0 && gy < HH && gx >= 0 && gx < WW) ? ip[gy * WW + gx] : 0.f;
    }
    __syncthreads();
    const int ry = threadIdx.y * 4;
    const int cx = threadIdx.x * 2;
    float acc0[4] = {0, 0, 0, 0}, acc1[4] = {0, 0, 0, 0};
    float kp[9];
#pragma unroll
    for (int a = 0; a < 10; a++) {
        float kc[9];
        if (a < 9) {
#pragma unroll
            for (int u = 0; u < 9; u++) kc[u] = sk[u * 9 + a];
        }
#pragma unroll
        for (int rr = 0; rr < 12; rr++) {
            float val = tile[(ry + rr) * 40 + cx + a];
#pragma unroll
            for (int k = 0; k < 4; k++) {
                int u = rr - k;
                if (u >= 0 && u <= 8) {
                    if (a < 9) acc0[k] += val * kc[u];
                    if (a >= 1) acc1[k] += val * kp[u];
                }
            }
        }
        if (a < 9) {
#pragma unroll
            for (int u = 0; u < 9; u++) kp[u] = kc[u];
        }
    }
#pragma unroll
    for (int k = 0; k < 4; k++) {
        int oy = Y0 + ry + k;
        if (oy < 2 || oy >= HH - 2) continue;
        int ox0 = X0 + cx, ox1 = ox0 + 1;
        size_t rowo = (size_t)bc * HWs + (size_t)oy * WW;
        if (ox0 >= 2 && ox0 < WW - 2) {
            if (accum) out[rowo + ox0] += acc0[k]; else out[rowo + ox0] = acc0[k];
        }
        if (ox1 >= 2 && ox1 < WW - 2) {
            if (accum) out[rowo + ox1] += acc1[k]; else out[rowo + ox1] = acc1[k];
        }
    }
}

// ------- exact two-stage sum_i kw_i K_i^T K_i on the 2-pixel border frame -------
// grid (48, 1, 12): blockIdx.x = side*12+seg; 256 threads
__global__ __launch_bounds__(256)
void border_k(const float* __restrict__ in, float* __restrict__ out,
              const float* __restrict__ ks, const float* __restrict__ kw,
              int I, int accum)
{
    __shared__ float vsh[6 * 40];
    __shared__ float tsh[4 * 36];
    __shared__ float sk[IRK * 25];
    __shared__ float skw[IRK];
    const int bc = blockIdx.z;
    const int side = blockIdx.x / 12, seg = blockIdx.x % 12;
    const bool horiz = (side < 2);
    const bool farside = (side & 1);
    const int tid = threadIdx.x;
    for (int k = tid; k < I * 25; k += 256) sk[k] = ks[k];
    if (tid < I) skw[tid] = kw[tid];
    const float* ip = in + (size_t)bc * HWs;
    const int lbase = seg * 32;
    if (tid < 240) {
        int i = tid / 40, j = tid % 40;
        int thin = (farside ? 378 : 0) + i;
        int lng = lbase - 4 + j;
        int gy = horiz ? thin : lng;
        int gx = horiz ? lng : thin;
        vsh[tid] = (gy >= 0 && gy < HH && gx >= 0 && gx < WW) ? ip[gy * WW + gx] : 0.f;
    }
    __syncthreads();
    float acc = 0.f;
    for (int i = 0; i < I; i++) {
        __syncthreads();
        if (tid < 144) {
            int it = tid / 36, jt = tid % 36;
            int glong = lbase - 2 + jt;
            float t = 0.f;
            if (glong >= 0 && glong < 384) {
#pragma unroll
                for (int a = 0; a < 5; a++) {
                    int vi = it + a + (farside ? 0 : -2);
                    if (vi >= 0 && vi < 6) {
#pragma unroll
                        for (int b = 0; b < 5; b++) {
                            float kv = horiz ? sk[i * 25 + a * 5 + b] : sk[i * 25 + b * 5 + a];
                            t += kv * vsh[vi * 40 + jt + b];
                        }
                    }
                }
            }
            tsh[tid] = t;
        }
        __syncthreads();
        if (tid < 64) {
            int io = tid / 32, jo = tid % 32;
            float s = 0.f;
#pragma unroll
            for (int a = 0; a < 5; a++) {
                int it = io + (farside ? 4 : 2) - a;
                if (it >= 0 && it < 4) {
#pragma unroll
                    for (int b = 0; b < 5; b++) {
                        int jt = jo + 4 - b;
                        float kv = horiz ? sk[i * 25 + a * 5 + b] : sk[i * 25 + b * 5 + a];
                        s += kv * tsh[it * 36 + jt];
                    }
                }
            }
            acc += skw[i] * s;
        }
    }
    if (tid < 64) {
        int io = tid / 32, jo = tid % 32;
        int thin = (farside ? 382 : 0) + io;
        int lng = lbase + jo;
        int gy = horiz ? thin : lng;
        int gx = horiz ? lng : thin;
        size_t o = (size_t)bc * HWs + (size_t)gy * WW + gx;
        if (accum) out[o] += acc; else out[o] = acc;
    }
}

// -------- fused out += sum_i K_i^T ( kw_i * wreg_i * (K_i v) ), exact, iter-1 reg --------
__global__ __launch_bounds__(288)
void ata_k(const float* __restrict__ in, float* __restrict__ out,
           const float* __restrict__ ks, const float* __restrict__ kw,
           const float* __restrict__ wreg, int I, int accum)
{
    __shared__ float vt[40 * 40];
    __shared__ float tt[36 * 36];
    __shared__ float sk[IRK * 25];
    __shared__ float skw[IRK];
    const int bc = blockIdx.z;
    const float* ip = in + (size_t)bc * HWs;
    const int tid = threadIdx.y * 36 + threadIdx.x;
    for (int k = tid; k < I * 25; k += 288) sk[k] = ks[k];
    if (tid < I) skw[tid] = kw[tid];
    const int X0 = blockIdx.x * 32, Y0 = blockIdx.y * 32;
    for (int k = tid; k < 40 * 40; k += 288) {
        int sy = k / 40, sx = k % 40;
        int gy = Y0 - 4 + sy, gx = X0 - 4 + sx;
        vt[k] = (gy >= 0 && gy < HH && gx >= 0 && gx < WW) ? ip[gy * WW + gx] : 0.f;
    }
    __syncthreads();
    const int tx = threadIdx.x;
    const int ty = threadIdx.y;
    const int syb = ty * 5;
    float a0 = 0, a1 = 0, a2 = 0, a3 = 0;
    for (int i = 0; i < I; i++) {
        float kr[25];
#pragma unroll
        for (int k = 0; k < 25; k++) kr[k] = sk[i * 25 + k];
        const float kwv = skw[i];
        __syncthreads();
        float tv0 = 0, tv1 = 0, tv2 = 0, tv3 = 0, tv4 = 0;
#pragma unroll
        for (int v = 0; v < 5; v++) {
#pragma unroll
            for (int rr = 0; rr < 9; rr++) {
                float val = vt[(syb + rr) * 40 + tx + v];
                int u;
                u = rr;     if (u <= 4)            tv0 += val * kr[u * 5 + v];
                u = rr - 1; if (u >= 0 && u <= 4)  tv1 += val * kr[u * 5 + v];
                u = rr - 2; if (u >= 0 && u <= 4)  tv2 += val * kr[u * 5 + v];
                u = rr - 3; if (u >= 0 && u <= 4)  tv3 += val * kr[u * 5 + v];
                u = rr - 4; if (u >= 0)            tv4 += val * kr[u * 5 + v];
            }
        }
        {
            float tvs[5] = {tv0, tv1, tv2, tv3, tv4};
#pragma unroll
            for (int k = 0; k < 5; k++) {
                int sy = syb + k;
                if (sy < 36) {
                    int gy = Y0 - 2 + sy, gx = X0 - 2 + tx;
                    float o = 0.f;
                    if (gy >= 0 && gy < HH && gx >= 0 && gx < WW) {
                        float w = kwv;
                        if (wreg) w *= wreg[((size_t)(bc * IRK + i)) * HWs + (size_t)gy * WW + gx];
                        o = tvs[k] * w;
                    }
                    tt[sy * 36 + tx] = o;
                }
            }
        }
        __syncthreads();
        if (tx < 32) {
            const int ry = ty * 4;
#pragma unroll
            for (int v = 0; v < 5; v++) {
                int col = tx + 4 - v;
#pragma unroll
                for (int rr = 0; rr < 8; rr++) {
                    float val = tt[(ry + rr) * 36 + col];
                    int u;
                    u = 4 - rr; if (u >= 0 && u <= 4) a0 += val * kr[u * 5 + v];
                    u = 5 - rr; if (u >= 0 && u <= 4) a1 += val * kr[u * 5 + v];
                    u = 6 - rr; if (u >= 0 && u <= 4) a2 += val * kr[u * 5 + v];
                    u = 7 - rr; if (u >= 0 && u <= 4) a3 += val * kr[u * 5 + v];
                }
            }
        }
    }
    if (tx < 32) {
        const int ry = ty * 4;
        float accs[4] = {a0, a1, a2, a3};
#pragma unroll
        for (int k2 = 0; k2 < 4; k2++) {
            size_t o = (size_t)bc * HWs + (size_t)(Y0 + ry + k2) * WW + X0 + tx;
            if (accum) out[o] += accs[k2]; else out[o] = accs[k2];
        }
    }
}

// -------- GMM reweighting --------
__global__ __launch_bounds__(256)
void gmm_k(const float* __restrict__ x, const float* __restrict__ rks,
           const float* __restrict__ gw, const float* __restrict__ giv)
{
    __shared__ float tile[36 * 36];
    __shared__ float sk[IRK * 25];
    const int bc = blockIdx.z;
    const float* ip = x + (size_t)bc * HWs;
    const int tid = threadIdx.y * 32 + threadIdx.x;
    for (int k = tid; k < IRK * 25; k += 256) sk[k] = rks[k];
    const int X0 = blockIdx.x * 32, Y0 = blockIdx.y * 32;
    for (int k = tid; k < 36 * 36; k += 256) {
        int sy = k / 36, sx = k % 36;
        int gy = Y0 - 2 + sy, gx = X0 - 2 + sx;
        tile[k] = (gy >= 0 && gy < HH && gx >= 0 && gx < WW) ? ip[gy * WW + gx] : 0.f;
    }
    __syncthreads();
    const int ry = threadIdx.y * 4, tx = threadIdx.x;
    for (int j = 0; j < IRK; j++) {
        float kr[25];
#pragma unroll
        for (int k = 0; k < 25; k++) kr[k] = sk[j * 25 + k];
        float g0 = 0, g1 = 0, g2 = 0, g3 = 0;
#pragma unroll
        for (int v = 0; v < 5; v++) {
#pragma unroll
            for (int rr = 0; rr < 8; rr++) {
                float val = tile[(ry + rr) * 36 + tx + v];
                int u;
                u = rr;     if (u <= 4)           g0 += val * kr[u * 5 + v];
                u = rr - 1; if (u >= 0 && u <= 4) g1 += val * kr[u * 5 + v];
                u = rr - 2; if (u >= 0 && u <= 4) g2 += val * kr[u * 5 + v];
                u = rr - 3; if (u >= 0)           g3 += val * kr[u * 5 + v];
            }
        }
        float iv0 = giv[0 * IRK + j], iv1 = giv[1 * IRK + j], iv2 = giv[2 * IRK + j];
        float c0 = gw[0 * IRK + j] * sqrtf(iv0);
        float c1 = gw[1 * IRK + j] * sqrtf(iv1);
        float c2 = gw[2 * IRK + j] * sqrtf(iv2);
        float gs[4] = {g0, g1, g2, g3};
#pragma unroll
        for (int k2 = 0; k2 < 4; k2++) {
            float gv = gs[k2];
            float p0 = c0 * expf(-0.5f * iv0 * gv * gv);
            float p1 = c1 * expf(-0.5f * iv1 * gv * gv);
            float p2 = c2 * expf(-0.5f * iv2 * gv * gv);
            float num = p0 * iv0 + p1 * iv1 + p2 * iv2;
            float den = p0 + p1 + p2 + 1e-12f;
            d_wreg[((size_t)(bc * IRK + j)) * HWs + (size_t)(Y0 + ry + k2) * WW + X0 + tx] = num / den;
        }
    }
}

// ---------------- CG vector/reduction kernels ----------------
__device__ __forceinline__ void blockStore256(float s, int b, int bx) {
    __shared__ float sm[8];
    s = warpRed(s);
    if ((threadIdx.x & 31) == 0) sm[threadIdx.x >> 5] = s;
    __syncthreads();
    if (threadIdx.x == 0) {
        float v = 0;
#pragma unroll
        for (int i = 0; i < 8; i++) v += sm[i];
        d_part[b * 512 + bx] = v;
    }
}

__global__ __launch_bounds__(256)
void resid_init_k() {
    const int b = blockIdx.y;
    size_t base = (size_t)b * NBE + (size_t)blockIdx.x * 1024 + threadIdx.x;
    float s = 0;
#pragma unroll
    for (int k = 0; k < 4; k++) {
        size_t idx = base + (size_t)k * 256;
        float rv = d_b[idx] - d_Ap[idx];
        d_r[idx] = rv; d_p[idx] = rv;
        s += rv * rv;
    }
    blockStore256(s, b, blockIdx.x);
}

__global__ __launch_bounds__(256)
void dot_k() {
    const int b = blockIdx.y;
    size_t base = (size_t)b * NBE + (size_t)blockIdx.x * 1024 + threadIdx.x;
    float s = 0;
#pragma unroll
    for (int k = 0; k < 4; k++) {
        size_t idx = base + (size_t)k * 256;
        s += d_p[idx] * d_Ap[idx];
    }
    blockStore256(s, b, blockIdx.x);
}

__global__ __launch_bounds__(256)
void update_xr_k(float* __restrict__ x) {
    const int b = blockIdx.y;
    const float alpha = d_scal[4 + b];
    size_t base = (size_t)b * NBE + (size_t)blockIdx.x * 1024 + threadIdx.x;
    float s = 0;
#pragma unroll
    for (int k = 0; k < 4; k++) {
        size_t idx = base + (size_t)k * 256;
        x[idx] += alpha * d_p[idx];
        float rv = d_r[idx] - alpha * d_Ap[idx];
        d_r[idx] = rv;
        s += rv * rv;
    }
    blockStore256(s, b, blockIdx.x);
}

__global__ __launch_bounds__(256)
void update_p_k() {
    const int b = blockIdx.y;
    const float beta = d_scal[8 + b];
    const int active = d_scal[12 + b] != 0.f;
    size_t base = (size_t)b * NBE + (size_t)blockIdx.x * 1024 + threadIdx.x;
#pragma unroll
    for (int k = 0; k < 4; k++) {
        size_t idx = base + (size_t)k * 256;
        if (active) d_p[idx] = d_r[idx] + beta * d_p[idx];
    }
}

__device__ __forceinline__ float reducePart(int b) {
    int t = threadIdx.x;
    float s = 0;
    for (int i = t; i < NPART; i += 256) s += d_part[b * 512 + i];
    __shared__ float sm[8];
    s = warpRed(s);
    if ((t & 31) == 0) sm[t >> 5] = s;
    __syncthreads();
    float v = 0;
    if (t == 0) {
#pragma unroll
        for (int i = 0; i < 8; i++) v += sm[i];
    }
    return v;
}

__global__ void scal_rs_k() {
    int b = blockIdx.x;
    float v = reducePart(b);
    if (threadIdx.x == 0) d_scal[b] = v;
}

__global__ void scal_alpha_k() {
    int b = blockIdx.x;
    float pAp = reducePart(b);
    if (threadIdx.x == 0) {
        float rs = d_scal[b];
        int active = sqrtf(rs) > 1e-6f;
        d_scal[12 + b] = active ? 1.f : 0.f;
        d_scal[4 + b] = active ? rs / fmaxf(pAp, 1e-12f) : 0.f;
    }
}

__global__ void scal_beta_k() {
    int b = blockIdx.x;
    float rs_new = reducePart(b);
    if (threadIdx.x == 0) {
        float rs = d_scal[b];
        int active = d_scal[12 + b] != 0.f;
        d_scal[8 + b] = active ? rs_new / fmaxf(rs, 1e-12f) : 0.f;
        d_scal[b] = active ? rs_new : rs;
    }
}

// ---------------- host orchestration ----------------
struct Ptrs {
    float *b, *Ap, *t1, *t2, *wreg, *p, *S;
};

static void Aop(const float* v, float* out, const float* kern,
                const float* dks, const float* dkw,
                const float* rks, const float* rkw,
                int use_wreg, const Ptrs& P)
{
    dim3 g(12, 12, NBC);
    dim3 bsm(16, 8);
    dim3 gb(48, 1, NBC);
    // data term: K^T (D^T W_d D) K v
    corr11_k<<<g, bsm>>>(v, P.t1, kern, 0);
    conv9_k<<<g, bsm>>>(P.t1, P.t2, P.S, 0);
    border_k<<<gb, 256>>>(P.t1, P.t2, dks, dkw, 8, 0);
    corr11_k<<<g, bsm>>>(P.t2, out, kern, 1);
    // reg term
    if (!use_wreg) {
        conv9_k<<<g, bsm>>>(v, out, P.S + 81, 1);
        border_k<<<gb, 256>>>(v, out, rks, rkw, IRK, 1);
    } else {
        ata_k<<<g, dim3(36, 8)>>>(v, out, rks, rkw, P.wreg, IRK, 1);
    }
}

extern "C" void kernel_launch(void* const* d_in, const int* in_sizes, int n_in,
                              void* d_out, int out_size)
{
    const float* blurred = (const float*)d_in[0];
    const float* kern    = (const float*)d_in[1];
    const float* dkw     = (const float*)d_in[2];
    const float* dks     = (const float*)d_in[3];
    const float* rkw     = (const float*)d_in[4];
    const float* rks     = (const float*)d_in[5];
    const float* gmmw    = (const float*)d_in[6];
    const float* gmmiv   = (const float*)d_in[7];
    float* x = (float*)d_out;

    Ptrs P;
    cudaGetSymbolAddress((void**)&P.b, d_b);
    cudaGetSymbolAddress((void**)&P.Ap, d_Ap);
    cudaGetSymbolAddress((void**)&P.t1, d_t1);
    cudaGetSymbolAddress((void**)&P.t2, d_t2);
    cudaGetSymbolAddress((void**)&P.wreg, d_wreg);
    cudaGetSymbolAddress((void**)&P.p, d_p);
    cudaGetSymbolAddress((void**)&P.S, d_S);

    const int n_irls = 2, n_cg = 8;
    dim3 g(12, 12, NBC);
    dim3 bsm(16, 8);
    dim3 gb(48, 1, NBC);
    dim3 gr(NPART, BB);

    autocorr_k<<<1, 256>>>(dks, dkw, rks, rkw);

    // x = blurred
    cudaMemcpyAsync(x, blurred, (size_t)NTOT * sizeof(float),
                    cudaMemcpyDeviceToDevice, 0);

    // b = K^T D^T W_d D blurred (IRLS-invariant: reg_targets == 0)
    conv9_k<<<g, bsm>>>(blurred, P.t1, P.S, 0);
    border_k<<<gb, 256>>>(blurred, P.t1, dks, dkw, 8, 0);
    corr11_k<<<g, bsm>>>(P.t1, P.b, kern, 1);

    for (int it = 0; it < n_irls; it++) {
        int use_wreg = (it != 0);
        if (it == 1)
            gmm_k<<<g, dim3(32, 8)>>>(x, rks, gmmw, gmmiv);

        Aop(x, P.Ap, kern, dks, dkw, rks, rkw, use_wreg, P);
        resid_init_k<<<gr, 256>>>();
        scal_rs_k<<<BB, 256>>>();

        for (int s = 0; s < n_cg; s++) {
            Aop(P.p, P.Ap, kern, dks, dkw, rks, rkw, use_wreg, P);
            dot_k<<<gr, 256>>>();
            scal_alpha_k<<<BB, 256>>>();
            update_xr_k<<<gr, 256>>>(x);
            scal_beta_k<<<BB, 256>>>();
            update_p_k<<<gr, 256>>>();
        }
    }
}

// round 6
// speedup vs baseline: 1.7152x; 1.0282x over previous
#include <cuda_runtime.h>
#include <math.h>

#define BB 4
#define CC 3
#define HH 384
#define WW 384
#define HWs (HH*WW)
#define NBC 12
#define NTOT (NBC*HWs)
#define NBE (CC*HWs)
#define IRK 16
#define NP_CORR 216   // partials from corr11 epilogue: 72 blocks/bc * 3 cc
#define NP_UPD  432   // partials from update_xr

// ------------ static device scratch ------------
__device__ float d_b[NTOT];
__device__ float d_r[NTOT];
__device__ float d_p[NTOT];
__device__ float d_Ap[NTOT];
__device__ float d_t1[NTOT];
__device__ float d_t2[NTOT];
__device__ float d_wreg[(size_t)IRK * NTOT];
__device__ float d_part[BB * 512];
__device__ float d_scal[16]; // [0..3]=rs [4..7]=alpha [8..11]=beta [12..15]=active
__device__ float d_S[162];   // [0..80]=S_data  [81..161]=S_reg

__device__ __forceinline__ float warpRed(float v) {
#pragma unroll
    for (int o = 16; o > 0; o >>= 1) v += __shfl_down_sync(0xffffffffu, v, o);
    return v;
}

// block-level reduction of one float over 256 threads -> d_part[b*512+slot]
__device__ __forceinline__ void blockStoreP(int tid, float s, int b, int slot) {
    __shared__ float sm[8];
    s = warpRed(s);
    if ((tid & 31) == 0) sm[tid >> 5] = s;
    __syncthreads();
    if (tid == 0) {
        float v = 0;
#pragma unroll
        for (int i = 0; i < 8; i++) v += sm[i];
        d_part[b * 512 + slot] = v;
    }
}

// ------- build composed 9x9 kernels S(d) = sum_i kw_i sum_e k_i(e) k_i(e+d) -------
__global__ void autocorr_k(const float* __restrict__ dks, const float* __restrict__ dkw,
                           const float* __restrict__ rks, const float* __restrict__ rkw)
{
    int tid = threadIdx.x;
    if (tid < 162) {
        int which = tid / 81, t = tid % 81;
        const float* ks = which ? rks : dks;
        const float* kw = which ? rkw : dkw;
        int I = which ? 16 : 8;
        int dy = t / 9 - 4, dx = t % 9 - 4;
        float s = 0.f;
        for (int i = 0; i < I; i++) {
            float w = kw[i];
            for (int u = 0; u < 5; u++)
                for (int v = 0; v < 5; v++) {
                    int u2 = u + dy, v2 = v + dx;
                    if (u2 >= 0 && u2 < 5 && v2 >= 0 && v2 < 5)
                        s += w * ks[i * 25 + u * 5 + v] * ks[i * 25 + u2 * 5 + v2];
                }
        }
        d_S[which * 81 + t] = s;
    }
}

// ---------------- 11x11 per-batch correlation, SAME, zero pad ----------------
// 64x32 output tile, block (32,8)=256 threads, each 2 cols x 4 rows. grid (6,12,12)
// mode 0: out = acc
// mode 1: out += acc; partial dot (out_new * dv) -> d_part          (Aop(p))
// mode 2: Ap = out+acc; rv = d_b-Ap; d_r=d_p=rv; partial rv^2       (Aop(x) residual)
__global__ __launch_bounds__(256)
void corr11_k(const float* __restrict__ in, float* __restrict__ out,
              const float* __restrict__ kern, int flip, int mode,
              const float* __restrict__ dv)
{
    __shared__ float tile[74 * 42];
    __shared__ float sk[121];
    const int bc = blockIdx.z;
    const int bat = bc / CC;
    const float* ip = in + (size_t)bc * HWs;
    const int tid = threadIdx.y * 32 + threadIdx.x;
    if (tid < 121) sk[tid] = kern[bat * 121 + (flip ? 120 - tid : tid)];
    const int X0 = blockIdx.x * 64, Y0 = blockIdx.y * 32;
    for (int k = tid; k < 74 * 42; k += 256) {
        int sy = k / 74, sx = k % 74;
        int gy = Y0 - 5 + sy, gx = X0 - 5 + sx;
        tile[k] = (gy >= 0 && gy < HH && gx >= 0 && gx < WW) ? ip[gy * WW + gx] : 0.f;
    }
    __syncthreads();
    const int ry = threadIdx.y * 4;
    const int cx = threadIdx.x * 2;
    float acc0[4] = {0, 0, 0, 0}, acc1[4] = {0, 0, 0, 0};
    float kp[11];
#pragma unroll
    for (int a = 0; a < 12; a++) {
        float kc[11];
        if (a < 11) {
#pragma unroll
            for (int u = 0; u < 11; u++) kc[u] = sk[u * 11 + a];
        }
#pragma unroll
        for (int rr = 0; rr < 14; rr++) {
            float val = tile[(ry + rr) * 74 + cx + a];
#pragma unroll
            for (int k = 0; k < 4; k++) {
                int u = rr - k;
                if (u >= 0 && u <= 10) {
                    if (a < 11) acc0[k] += val * kc[u];
                    if (a >= 1) acc1[k] += val * kp[u];
                }
            }
        }
        if (a < 11) {
#pragma unroll
            for (int u = 0; u < 11; u++) kp[u] = kc[u];
        }
    }
    size_t obase = (size_t)bc * HWs + (size_t)(Y0 + ry) * WW + X0 + cx;
    if (mode == 0) {
#pragma unroll
        for (int k = 0; k < 4; k++) {
            out[obase + (size_t)k * WW] = acc0[k];
            out[obase + (size_t)k * WW + 1] = acc1[k];
        }
    } else {
        float s = 0.f;
        if (mode == 1) {
#pragma unroll
            for (int k = 0; k < 4; k++) {
                size_t o = obase + (size_t)k * WW;
                float a0 = out[o] + acc0[k]; out[o] = a0; s += a0 * dv[o];
                o++;
                float a1 = out[o] + acc1[k]; out[o] = a1; s += a1 * dv[o];
            }
        } else {
#pragma unroll
            for (int k = 0; k < 4; k++) {
                size_t o = obase + (size_t)k * WW;
                float a0 = out[o] + acc0[k];
                float rv0 = d_b[o] - a0; d_r[o] = rv0; d_p[o] = rv0; s += rv0 * rv0;
                o++;
                float a1 = out[o] + acc1[k];
                float rv1 = d_b[o] - a1; d_r[o] = rv1; d_p[o] = rv1; s += rv1 * rv1;
            }
        }
        int slot = (bc % CC) * 72 + blockIdx.y * 6 + blockIdx.x;
        blockStoreP(tid, s, bat, slot);
    }
}

// ------- composed 9x9 conv (interior) + exact two-stage border, single launch -------
// grid (6, 20, 12): blockIdx.y<12 -> interior 64x32 tile (block 32x8)
//                   blockIdx.y>=12 -> border segment (48 segs = (y-12)*6+x)
__global__ __launch_bounds__(256)
void conv9F_k(const float* __restrict__ in, float* __restrict__ out,
              const float* __restrict__ S,
              const float* __restrict__ ks, const float* __restrict__ kw, int I)
{
    __shared__ float tile[72 * 40];
    __shared__ float sk9[81];
    const int bc = blockIdx.z;
    const float* ip = in + (size_t)bc * HWs;
    const int tid = threadIdx.y * 32 + threadIdx.x;

    if (blockIdx.y >= 12) {
        // -------- exact two-stage border path (writes dist<2 pixels) --------
        float* vsh = tile;          // 6*40 = 240
        float* tsh = tile + 256;    // 4*36 = 144
        float* sk5 = tile + 512;    // I*25 <= 400
        float* skw = tile + 1024;   // I
        const int bseg = (blockIdx.y - 12) * 6 + blockIdx.x; // 0..47
        const int side = bseg / 12, seg = bseg % 12;
        const bool horiz = (side < 2);
        const bool farside = (side & 1);
        for (int k = tid; k < I * 25; k += 256) sk5[k] = ks[k];
        if (tid < I) skw[tid] = kw[tid];
        const int lbase = seg * 32;
        if (tid < 240) {
            int i = tid / 40, j = tid % 40;
            int thin = (farside ? 378 : 0) + i;
            int lng = lbase - 4 + j;
            int gy = horiz ? thin : lng;
            int gx = horiz ? lng : thin;
            vsh[tid] = (gy >= 0 && gy < HH && gx >= 0 && gx < WW) ? ip[gy * WW + gx] : 0.f;
        }
        __syncthreads();
        float acc = 0.f;
        for (int i = 0; i < I; i++) {
            __syncthreads();
            if (tid < 144) {
                int it = tid / 36, jt = tid % 36;
                int glong = lbase - 2 + jt;
                float t = 0.f;
                if (glong >= 0 && glong < 384) {
#pragma unroll
                    for (int a = 0; a < 5; a++) {
                        int vi = it + a + (farside ? 0 : -2);
                        if (vi >= 0 && vi < 6) {
#pragma unroll
                            for (int b2 = 0; b2 < 5; b2++) {
                                float kv = horiz ? sk5[i * 25 + a * 5 + b2] : sk5[i * 25 + b2 * 5 + a];
                                t += kv * vsh[vi * 40 + jt + b2];
                            }
                        }
                    }
                }
                tsh[tid] = t;
            }
            __syncthreads();
            if (tid < 64) {
                int io = tid / 32, jo = tid % 32;
                float s = 0.f;
#pragma unroll
                for (int a = 0; a < 5; a++) {
                    int it = io + (farside ? 4 : 2) - a;
                    if (it >= 0 && it < 4) {
#pragma unroll
                        for (int b2 = 0; b2 < 5; b2++) {
                            int jt = jo + 4 - b2;
                            float kv = horiz ? sk5[i * 25 + a * 5 + b2] : sk5[i * 25 + b2 * 5 + a];
                            s += kv * tsh[it * 36 + jt];
                        }
                    }
                }
                acc += skw[i] * s;
            }
        }
        if (tid < 64) {
            int io = tid / 32, jo = tid % 32;
            int thin = (farside ? 382 : 0) + io;
            int lng = lbase + jo;
            int gy = horiz ? thin : lng;
            int gx = horiz ? lng : thin;
            out[(size_t)bc * HWs + (size_t)gy * WW + gx] = acc;
        }
        return;
    }

    // -------- interior composed 9x9 path --------
    if (tid < 81) sk9[tid] = S[tid];
    const int X0 = blockIdx.x * 64, Y0 = blockIdx.y * 32;
    for (int k = tid; k < 72 * 40; k += 256) {
        int sy = k / 72, sx = k % 72;
        int gy = Y0 - 4 + sy, gx = X0 - 4 + sx;
        tile[k] = (gy >= 0 && gy < HH && gx >= 0 && gx < WW) ? ip[gy * WW + gx] : 0.f;
    }
    __syncthreads();
    const int ry = threadIdx.y * 4;
    const int cx = threadIdx.x * 2;
    float acc0[4] = {0, 0, 0, 0}, acc1[4] = {0, 0, 0, 0};
    float kp[9];
#pragma unroll
    for (int a = 0; a < 10; a++) {
        float kc[9];
        if (a < 9) {
#pragma unroll
            for (int u = 0; u < 9; u++) kc[u] = sk9[u * 9 + a];
        }
#pragma unroll
        for (int rr = 0; rr < 12; rr++) {
            float val = tile[(ry + rr) * 72 + cx + a];
#pragma unroll
            for (int k = 0; k < 4; k++) {
                int u = rr - k;
                if (u >= 0 && u <= 8) {
                    if (a < 9) acc0[k] += val * kc[u];
                    if (a >= 1) acc1[k] += val * kp[u];
                }
            }
        }
        if (a < 9) {
#pragma unroll
            for (int u = 0; u < 9; u++) kp[u] = kc[u];
        }
    }
#pragma unroll
    for (int k = 0; k < 4; k++) {
        int oy = Y0 + ry + k;
        if (oy < 2 || oy >= HH - 2) continue;
        int ox0 = X0 + cx, ox1 = ox0 + 1;
        size_t rowo = (size_t)bc * HWs + (size_t)oy * WW;
        if (ox0 >= 2 && ox0 < WW - 2) out[rowo + ox0] = acc0[k];
        if (ox1 >= 2 && ox1 < WW - 2) out[rowo + ox1] = acc1[k];
    }
}

// -------- fused out = sum_i K_i^T ( kw_i * wreg_i * (K_i v) ) (iter-1 reg term) --------
__global__ __launch_bounds__(288)
void ata_k(const float* __restrict__ in, float* __restrict__ out,
           const float* __restrict__ ks, const float* __restrict__ kw,
           const float* __restrict__ wreg, int I, int accum)
{
    __shared__ float vt[40 * 40];
    __shared__ float tt[36 * 36];
    __shared__ float sk[IRK * 25];
    __shared__ float skw[IRK];
    const int bc = blockIdx.z;
    const float* ip = in + (size_t)bc * HWs;
    const int tid = threadIdx.y * 36 + threadIdx.x;
    for (int k = tid; k < I * 25; k += 288) sk[k] = ks[k];
    if (tid < I) skw[tid] = kw[tid];
    const int X0 = blockIdx.x * 32, Y0 = blockIdx.y * 32;
    for (int k = tid; k < 40 * 40; k += 288) {
        int sy = k / 40, sx = k % 40;
        int gy = Y0 - 4 + sy, gx = X0 - 4 + sx;
        vt[k] = (gy >= 0 && gy < HH && gx >= 0 && gx < WW) ? ip[gy * WW + gx] : 0.f;
    }
    __syncthreads();
    const int tx = threadIdx.x;
    const int ty = threadIdx.y;
    const int syb = ty * 5;
    float a0 = 0, a1 = 0, a2 = 0, a3 = 0;
    for (int i = 0; i < I; i++) {
        float kr[25];
#pragma unroll
        for (int k = 0; k < 25; k++) kr[k] = sk[i * 25 + k];
        const float kwv = skw[i];
        __syncthreads();
        float tv0 = 0, tv1 = 0, tv2 = 0, tv3 = 0, tv4 = 0;
#pragma unroll
        for (int v = 0; v < 5; v++) {
#pragma unroll
            for (int rr = 0; rr < 9; rr++) {
                float val = vt[(syb + rr) * 40 + tx + v];
                int u;
                u = rr;     if (u <= 4)            tv0 += val * kr[u * 5 + v];
                u = rr - 1; if (u >= 0 && u <= 4)  tv1 += val * kr[u * 5 + v];
                u = rr - 2; if (u >= 0 && u <= 4)  tv2 += val * kr[u * 5 + v];
                u = rr - 3; if (u >= 0 && u <= 4)  tv3 += val * kr[u * 5 + v];
                u = rr - 4; if (u >= 0)            tv4 += val * kr[u * 5 + v];
            }
        }
        {
            float tvs[5] = {tv0, tv1, tv2, tv3, tv4};
#pragma unroll
            for (int k = 0; k < 5; k++) {
                int sy = syb + k;
                if (sy < 36) {
                    int gy = Y0 - 2 + sy, gx = X0 - 2 + tx;
                    float o = 0.f;
                    if (gy >= 0 && gy < HH && gx >= 0 && gx < WW) {
                        float w = kwv;
                        if (wreg) w *= wreg[((size_t)(bc * IRK + i)) * HWs + (size_t)gy * WW + gx];
                        o = tvs[k] * w;
                    }
                    tt[sy * 36 + tx] = o;
                }
            }
        }
        __syncthreads();
        if (tx < 32) {
            const int ry = ty * 4;
#pragma unroll
            for (int v = 0; v < 5; v++) {
                int col = tx + 4 - v;
#pragma unroll
                for (int rr = 0; rr < 8; rr++) {
                    float val = tt[(ry + rr) * 36 + col];
                    int u;
                    u = 4 - rr; if (u >= 0 && u <= 4) a0 += val * kr[u * 5 + v];
                    u = 5 - rr; if (u >= 0 && u <= 4) a1 += val * kr[u * 5 + v];
                    u = 6 - rr; if (u >= 0 && u <= 4) a2 += val * kr[u * 5 + v];
                    u = 7 - rr; if (u >= 0 && u <= 4) a3 += val * kr[u * 5 + v];
                }
            }
        }
    }
    if (tx < 32) {
        const int ry = ty * 4;
        float accs[4] = {a0, a1, a2, a3};
#pragma unroll
        for (int k2 = 0; k2 < 4; k2++) {
            size_t o = (size_t)bc * HWs + (size_t)(Y0 + ry + k2) * WW + X0 + tx;
            if (accum) out[o] += accs[k2]; else out[o] = accs[k2];
        }
    }
}

// -------- GMM reweighting --------
__global__ __launch_bounds__(256)
void gmm_k(const float* __restrict__ x, const float* __restrict__ rks,
           const float* __restrict__ gw, const float* __restrict__ giv)
{
    __shared__ float tile[36 * 36];
    __shared__ float sk[IRK * 25];
    const int bc = blockIdx.z;
    const float* ip = x + (size_t)bc * HWs;
    const int tid = threadIdx.y * 32 + threadIdx.x;
    for (int k = tid; k < IRK * 25; k += 256) sk[k] = rks[k];
    const int X0 = blockIdx.x * 32, Y0 = blockIdx.y * 32;
    for (int k = tid; k < 36 * 36; k += 256) {
        int sy = k / 36, sx = k % 36;
        int gy = Y0 - 2 + sy, gx = X0 - 2 + sx;
        tile[k] = (gy >= 0 && gy < HH && gx >= 0 && gx < WW) ? ip[gy * WW + gx] : 0.f;
    }
    __syncthreads();
    const int ry = threadIdx.y * 4, tx = threadIdx.x;
    for (int j = 0; j < IRK; j++) {
        float kr[25];
#pragma unroll
        for (int k = 0; k < 25; k++) kr[k] = sk[j * 25 + k];
        float g0 = 0, g1 = 0, g2 = 0, g3 = 0;
#pragma unroll
        for (int v = 0; v < 5; v++) {
#pragma unroll
            for (int rr = 0; rr < 8; rr++) {
                float val = tile[(ry + rr) * 36 + tx + v];
                int u;
                u = rr;     if (u <= 4)           g0 += val * kr[u * 5 + v];
                u = rr - 1; if (u >= 0 && u <= 4) g1 += val * kr[u * 5 + v];
                u = rr - 2; if (u >= 0 && u <= 4) g2 += val * kr[u * 5 + v];
                u = rr - 3; if (u >= 0)           g3 += val * kr[u * 5 + v];
            }
        }
        float iv0 = giv[0 * IRK + j], iv1 = giv[1 * IRK + j], iv2 = giv[2 * IRK + j];
        float c0 = gw[0 * IRK + j] * sqrtf(iv0);
        float c1 = gw[1 * IRK + j] * sqrtf(iv1);
        float c2 = gw[2 * IRK + j] * sqrtf(iv2);
        float gs[4] = {g0, g1, g2, g3};
#pragma unroll
        for (int k2 = 0; k2 < 4; k2++) {
            float gv = gs[k2];
            float p0 = c0 * expf(-0.5f * iv0 * gv * gv);
            float p1 = c1 * expf(-0.5f * iv1 * gv * gv);
            float p2 = c2 * expf(-0.5f * iv2 * gv * gv);
            float num = p0 * iv0 + p1 * iv1 + p2 * iv2;
            float den = p0 + p1 + p2 + 1e-12f;
            d_wreg[((size_t)(bc * IRK + j)) * HWs + (size_t)(Y0 + ry + k2) * WW + X0 + tx] = num / den;
        }
    }
}

// ---------------- CG vector kernels (float4, deterministic) ----------------
// grid (432, BB), block 256; each block: 256 float4 = 1024 floats
__global__ __launch_bounds__(256)
void update_xr_k(float* __restrict__ x) {
    const int b = blockIdx.y;
    const float alpha = d_scal[4 + b];
    size_t i4 = ((size_t)b * NBE) / 4 + (size_t)blockIdx.x * 256 + threadIdx.x;
    float4* x4 = (float4*)x;
    float4* p4 = (float4*)d_p;
    float4* r4 = (float4*)d_r;
    float4* a4 = (float4*)d_Ap;
    float4 xv = x4[i4], pv = p4[i4], rv = r4[i4], av = a4[i4];
    xv.x += alpha * pv.x; xv.y += alpha * pv.y; xv.z += alpha * pv.z; xv.w += alpha * pv.w;
    rv.x -= alpha * av.x; rv.y -= alpha * av.y; rv.z -= alpha * av.z; rv.w -= alpha * av.w;
    x4[i4] = xv; r4[i4] = rv;
    float s = rv.x * rv.x + rv.y * rv.y + rv.z * rv.z + rv.w * rv.w;
    blockStoreP(threadIdx.x, s, b, blockIdx.x);
}

__global__ __launch_bounds__(256)
void update_p_k() {
    const int b = blockIdx.y;
    const float beta = d_scal[8 + b];
    const int active = d_scal[12 + b] != 0.f;
    if (!active) return;
    size_t i4 = ((size_t)b * NBE) / 4 + (size_t)blockIdx.x * 256 + threadIdx.x;
    float4* p4 = (float4*)d_p;
    float4* r4 = (float4*)d_r;
    float4 pv = p4[i4], rv = r4[i4];
    pv.x = rv.x + beta * pv.x; pv.y = rv.y + beta * pv.y;
    pv.z = rv.z + beta * pv.z; pv.w = rv.w + beta * pv.w;
    p4[i4] = pv;
}

// ---------------- scalar kernels: one block per batch ----------------
__device__ __forceinline__ float reducePart(int b, int n) {
    int t = threadIdx.x;
    float s = 0;
    for (int i = t; i < n; i += 256) s += d_part[b * 512 + i];
    __shared__ float sm[8];
    s = warpRed(s);
    if ((t & 31) == 0) sm[t >> 5] = s;
    __syncthreads();
    float v = 0;
    if (t == 0) {
#pragma unroll
        for (int i = 0; i < 8; i++) v += sm[i];
    }
    return v;
}

__global__ void scal_rs_k(int n) {
    int b = blockIdx.x;
    float v = reducePart(b, n);
    if (threadIdx.x == 0) d_scal[b] = v;
}

__global__ void scal_alpha_k(int n) {
    int b = blockIdx.x;
    float pAp = reducePart(b, n);
    if (threadIdx.x == 0) {
        float rs = d_scal[b];
        int active = sqrtf(rs) > 1e-6f;
        d_scal[12 + b] = active ? 1.f : 0.f;
        d_scal[4 + b] = active ? rs / fmaxf(pAp, 1e-12f) : 0.f;
    }
}

__global__ void scal_beta_k(int n) {
    int b = blockIdx.x;
    float rs_new = reducePart(b, n);
    if (threadIdx.x == 0) {
        float rs = d_scal[b];
        int active = d_scal[12 + b] != 0.f;
        d_scal[8 + b] = active ? rs_new / fmaxf(rs, 1e-12f) : 0.f;
        d_scal[b] = active ? rs_new : rs;
    }
}

// ---------------- host orchestration ----------------
struct Ptrs {
    float *b, *Ap, *t1, *t2, *wreg, *p, *S;
};

// out = A v; mode_final: 1 = fuse dot(Ap, dv); 2 = fuse residual init (r=b-Ap, p=r, rs)
static void Aop(const float* v, float* out, int iter, int mode_final, const float* dv,
                const Ptrs& P, const float* kern,
                const float* dks, const float* dkw,
                const float* rks, const float* rkw)
{
    dim3 gc(6, 12, NBC), bl(32, 8);
    dim3 gf(6, 20, NBC);
    // reg term first (plain write)
    if (iter == 0)
        conv9F_k<<<gf, bl>>>(v, out, P.S + 81, rks, rkw, IRK);
    else
        ata_k<<<dim3(12, 12, NBC), dim3(36, 8)>>>(v, out, rks, rkw, P.wreg, IRK, 0);
    // data term: K^T S_d K v, accumulated by the final corr11 (fused epilogue)
    corr11_k<<<gc, bl>>>(v, P.t1, kern, 0, 0, nullptr);
    conv9F_k<<<gf, bl>>>(P.t1, P.t2, P.S, dks, dkw, 8);
    corr11_k<<<gc, bl>>>(P.t2, out, kern, 1, mode_final, dv);
}

extern "C" void kernel_launch(void* const* d_in, const int* in_sizes, int n_in,
                              void* d_out, int out_size)
{
    const float* blurred = (const float*)d_in[0];
    const float* kern    = (const float*)d_in[1];
    const float* dkw     = (const float*)d_in[2];
    const float* dks     = (const float*)d_in[3];
    const float* rkw     = (const float*)d_in[4];
    const float* rks     = (const float*)d_in[5];
    const float* gmmw    = (const float*)d_in[6];
    const float* gmmiv   = (const float*)d_in[7];
    float* x = (float*)d_out;

    Ptrs P;
    cudaGetSymbolAddress((void**)&P.b, d_b);
    cudaGetSymbolAddress((void**)&P.Ap, d_Ap);
    cudaGetSymbolAddress((void**)&P.t1, d_t1);
    cudaGetSymbolAddress((void**)&P.t2, d_t2);
    cudaGetSymbolAddress((void**)&P.wreg, d_wreg);
    cudaGetSymbolAddress((void**)&P.p, d_p);
    cudaGetSymbolAddress((void**)&P.S, d_S);

    const int n_irls = 2, n_cg = 8;
    dim3 gc(6, 12, NBC), bl(32, 8);
    dim3 gf(6, 20, NBC);
    dim3 gu(432, BB);

    autocorr_k<<<1, 256>>>(dks, dkw, rks, rkw);

    // x = blurred
    cudaMemcpyAsync(x, blurred, (size_t)NTOT * sizeof(float),
                    cudaMemcpyDeviceToDevice, 0);

    // b = K^T S_d blurred (+ exact border); IRLS-invariant since reg_targets == 0
    conv9F_k<<<gf, bl>>>(blurred, P.t1, P.S, dks, dkw, 8);
    corr11_k<<<gc, bl>>>(P.t1, P.b, kern, 1, 0, nullptr);

    for (int it = 0; it < n_irls; it++) {
        if (it == 1)
            gmm_k<<<dim3(12, 12, NBC), dim3(32, 8)>>>(x, rks, gmmw, gmmiv);

        // residual init fused into final corr11 of Aop(x)
        Aop(x, P.Ap, it, 2, nullptr, P, kern, dks, dkw, rks, rkw);
        scal_rs_k<<<BB, 256>>>(NP_CORR);

        for (int s = 0; s < n_cg; s++) {
            Aop(P.p, P.Ap, it, 1, P.p, P, kern, dks, dkw, rks, rkw);
            scal_alpha_k<<<BB, 256>>>(NP_CORR);
            update_xr_k<<<gu, 256>>>(x);
            scal_beta_k<<<BB, 256>>>(NP_UPD);
            update_p_k<<<gu, 256>>>();
        }
    }
}

// round 7
// speedup vs baseline: 1.7288x; 1.0079x over previous
#include <cuda_runtime.h>
#include <math.h>

#define BB 4
#define CC 3
#define HH 384
#define WW 384
#define HWs (HH*WW)
#define NBC 12
#define NTOT (NBC*HWs)
#define NBE (CC*HWs)
#define IRK 16
#define NP_CORR 216   // corr11 blocks per batch (6*12*3)
#define NP_UPD  432   // update_xr blocks per batch

// ------------ static device scratch ------------
__device__ float d_b[NTOT];
__device__ float d_r[NTOT];
__device__ float d_p[NTOT];
__device__ float d_Ap[NTOT];
__device__ float d_t1[NTOT];
__device__ float d_t2[NTOT];
__device__ float d_wreg[(size_t)IRK * NTOT];
__device__ float d_part[BB * 512];
__device__ float d_scal[16]; // [0..3]=rs [4..7]=alpha [8..11]=beta [12..15]=active
__device__ float d_S[162];   // [0..80]=S_data  [81..161]=S_reg
__device__ int   d_cnt[8];   // per-batch completion counters (self-resetting)

__device__ __forceinline__ float warpRed(float v) {
#pragma unroll
    for (int o = 16; o > 0; o >>= 1) v += __shfl_down_sync(0xffffffffu, v, o);
    return v;
}

// Block-reduce s, store partial, detect last block of batch b, then cooperatively
// reduce all nblk partials. Returns true on ALL 256 threads of the last block;
// *tot then holds the full per-batch sum (identical on all threads).
__device__ __forceinline__ bool lastBlockTotal(int tid, float s, int b, int slot,
                                               int nblk, float* tot) {
    __shared__ float sm[8];
    __shared__ int lastF;
    float w = warpRed(s);
    if ((tid & 31) == 0) sm[tid >> 5] = w;
    __syncthreads();
    if (tid == 0) {
        float v = 0;
#pragma unroll
        for (int i = 0; i < 8; i++) v += sm[i];
        d_part[b * 512 + slot] = v;
        __threadfence();
        int old = atomicAdd(&d_cnt[b], 1);
        lastF = (old == nblk - 1);
        if (lastF) d_cnt[b] = 0;
    }
    __syncthreads();
    if (!lastF) return false;
    float t = 0;
    for (int i = tid; i < nblk; i += 256) t += d_part[b * 512 + i];
    t = warpRed(t);
    __syncthreads();
    if ((tid & 31) == 0) sm[tid >> 5] = t;
    __syncthreads();
    float v = 0;
#pragma unroll
    for (int i = 0; i < 8; i++) v += sm[i];
    *tot = v;
    return true;
}

// ------- build composed 9x9 kernels S(d) = sum_i kw_i sum_e k_i(e) k_i(e+d) -------
__global__ void autocorr_k(const float* __restrict__ dks, const float* __restrict__ dkw,
                           const float* __restrict__ rks, const float* __restrict__ rkw)
{
    int tid = threadIdx.x;
    if (tid < 162) {
        int which = tid / 81, t = tid % 81;
        const float* ks = which ? rks : dks;
        const float* kw = which ? rkw : dkw;
        int I = which ? 16 : 8;
        int dy = t / 9 - 4, dx = t % 9 - 4;
        float s = 0.f;
        for (int i = 0; i < I; i++) {
            float w = kw[i];
            for (int u = 0; u < 5; u++)
                for (int v = 0; v < 5; v++) {
                    int u2 = u + dy, v2 = v + dx;
                    if (u2 >= 0 && u2 < 5 && v2 >= 0 && v2 < 5)
                        s += w * ks[i * 25 + u * 5 + v] * ks[i * 25 + u2 * 5 + v2];
                }
        }
        d_S[which * 81 + t] = s;
    }
}

// ---------------- 11x11 per-batch correlation, SAME, zero pad ----------------
// 64x32 tile, block (32,8). thread tx covers cols tx and tx+32 (conflict-free LDS).
// mode 0: out = acc
// mode 1: out += acc; fused dot(out_new, dv); last block computes alpha/active
// mode 2: Ap = out+acc; rv=b-Ap; r=p=rv; fused rs; last block stores rs
__global__ __launch_bounds__(256)
void corr11_k(const float* __restrict__ in, float* __restrict__ out,
              const float* __restrict__ kern, int flip, int mode,
              const float* __restrict__ dv)
{
    __shared__ float tile[42 * 74];
    __shared__ float sk[121];
    const int bc = blockIdx.z;
    const int bat = bc / CC;
    const float* ip = in + (size_t)bc * HWs;
    const int tid = threadIdx.y * 32 + threadIdx.x;
    if (tid < 121) sk[tid] = kern[bat * 121 + (flip ? 120 - tid : tid)];
    const int X0 = blockIdx.x * 64, Y0 = blockIdx.y * 32;
    for (int k = tid; k < 42 * 74; k += 256) {
        int sy = k / 74, sx = k % 74;
        int gy = Y0 - 5 + sy, gx = X0 - 5 + sx;
        tile[k] = (gy >= 0 && gy < HH && gx >= 0 && gx < WW) ? ip[gy * WW + gx] : 0.f;
    }
    __syncthreads();
    const int ry = threadIdx.y * 4;
    const int tx = threadIdx.x;
    float acc0[4] = {0, 0, 0, 0}, acc1[4] = {0, 0, 0, 0};
#pragma unroll
    for (int a = 0; a < 11; a++) {
        float kc[11];
#pragma unroll
        for (int u = 0; u < 11; u++) kc[u] = sk[u * 11 + a];
#pragma unroll
        for (int rr = 0; rr < 14; rr++) {
            float v0 = tile[(ry + rr) * 74 + tx + a];
            float v1 = tile[(ry + rr) * 74 + tx + 32 + a];
#pragma unroll
            for (int k = 0; k < 4; k++) {
                int u = rr - k;
                if (u >= 0 && u <= 10) {
                    acc0[k] += v0 * kc[u];
                    acc1[k] += v1 * kc[u];
                }
            }
        }
    }
    size_t obase = (size_t)bc * HWs + (size_t)(Y0 + ry) * WW + X0 + tx;
    if (mode == 0) {
#pragma unroll
        for (int k = 0; k < 4; k++) {
            out[obase + (size_t)k * WW] = acc0[k];
            out[obase + (size_t)k * WW + 32] = acc1[k];
        }
        return;
    }
    float s = 0.f;
    if (mode == 1) {
#pragma unroll
        for (int k = 0; k < 4; k++) {
            size_t o = obase + (size_t)k * WW;
            float a0 = out[o] + acc0[k]; out[o] = a0; s += a0 * dv[o];
            size_t o1 = o + 32;
            float a1 = out[o1] + acc1[k]; out[o1] = a1; s += a1 * dv[o1];
        }
    } else {
#pragma unroll
        for (int k = 0; k < 4; k++) {
            size_t o = obase + (size_t)k * WW;
            float a0 = out[o] + acc0[k];
            float rv0 = d_b[o] - a0; d_r[o] = rv0; d_p[o] = rv0; s += rv0 * rv0;
            size_t o1 = o + 32;
            float a1 = out[o1] + acc1[k];
            float rv1 = d_b[o1] - a1; d_r[o1] = rv1; d_p[o1] = rv1; s += rv1 * rv1;
        }
    }
    int slot = (bc % CC) * 72 + blockIdx.y * 6 + blockIdx.x;
    float tot;
    if (lastBlockTotal(tid, s, bat, slot, NP_CORR, &tot)) {
        if (tid == 0) {
            if (mode == 2) {
                d_scal[bat] = tot;                 // rs
            } else {
                float rs = d_scal[bat];
                int act = sqrtf(rs) > 1e-6f;
                d_scal[12 + bat] = act ? 1.f : 0.f;
                d_scal[4 + bat] = act ? rs / fmaxf(tot, 1e-12f) : 0.f;  // alpha
            }
        }
    }
}

// ------- 9x9 composed conv, interior only (dist>=2). 64x32 tile, block (32,8) -------
__global__ __launch_bounds__(256)
void conv9_k(const float* __restrict__ in, float* __restrict__ out,
             const float* __restrict__ S)
{
    __shared__ float tile[40 * 72];
    __shared__ float sk[81];
    const int bc = blockIdx.z;
    const float* ip = in + (size_t)bc * HWs;
    const int tid = threadIdx.y * 32 + threadIdx.x;
    if (tid < 81) sk[tid] = S[tid];
    const int X0 = blockIdx.x * 64, Y0 = blockIdx.y * 32;
    for (int k = tid; k < 40 * 72; k += 256) {
        int sy = k / 72, sx = k % 72;
        int gy = Y0 - 4 + sy, gx = X0 - 4 + sx;
        tile[k] = (gy >= 0 && gy < HH && gx >= 0 && gx < WW) ? ip[gy * WW + gx] : 0.f;
    }
    __syncthreads();
    const int ry = threadIdx.y * 4;
    const int tx = threadIdx.x;
    float acc0[4] = {0, 0, 0, 0}, acc1[4] = {0, 0, 0, 0};
#pragma unroll
    for (int a = 0; a < 9; a++) {
        float kc[9];
#pragma unroll
        for (int u = 0; u < 9; u++) kc[u] = sk[u * 9 + a];
#pragma unroll
        for (int rr = 0; rr < 12; rr++) {
            float v0 = tile[(ry + rr) * 72 + tx + a];
            float v1 = tile[(ry + rr) * 72 + tx + 32 + a];
#pragma unroll
            for (int k = 0; k < 4; k++) {
                int u = rr - k;
                if (u >= 0 && u <= 8) {
                    acc0[k] += v0 * kc[u];
                    acc1[k] += v1 * kc[u];
                }
            }
        }
    }
#pragma unroll
    for (int k = 0; k < 4; k++) {
        int oy = Y0 + ry + k;
        if (oy < 2 || oy >= HH - 2) continue;
        size_t rowo = (size_t)bc * HWs + (size_t)oy * WW;
        int ox0 = X0 + tx, ox1 = ox0 + 32;
        if (ox0 >= 2 && ox0 < WW - 2) out[rowo + ox0] = acc0[k];
        if (ox1 >= 2 && ox1 < WW - 2) out[rowo + ox1] = acc1[k];
    }
}

// ------- exact two-stage sum_i kw_i K_i^T K_i on the 2-pixel border frame -------
// grid (48, 1, 12): blockIdx.x = side*12+seg; 256 threads. Plain writes.
__global__ __launch_bounds__(256)
void border_k(const float* __restrict__ in, float* __restrict__ out,
              const float* __restrict__ ks, const float* __restrict__ kw, int I)
{
    __shared__ float vsh[6 * 40];
    __shared__ float tsh[4 * 36];
    __shared__ float sk[IRK * 25];
    __shared__ float skw[IRK];
    const int bc = blockIdx.z;
    const int side = blockIdx.x / 12, seg = blockIdx.x % 12;
    const bool horiz = (side < 2);
    const bool farside = (side & 1);
    const int tid = threadIdx.x;
    for (int k = tid; k < I * 25; k += 256) sk[k] = ks[k];
    if (tid < I) skw[tid] = kw[tid];
    const float* ip = in + (size_t)bc * HWs;
    const int lbase = seg * 32;
    if (tid < 240) {
        int i = tid / 40, j = tid % 40;
        int thin = (farside ? 378 : 0) + i;
        int lng = lbase - 4 + j;
        int gy = horiz ? thin : lng;
        int gx = horiz ? lng : thin;
        vsh[tid] = (gy >= 0 && gy < HH && gx >= 0 && gx < WW) ? ip[gy * WW + gx] : 0.f;
    }
    __syncthreads();
    float acc = 0.f;
    for (int i = 0; i < I; i++) {
        __syncthreads();
        if (tid < 144) {
            int it = tid / 36, jt = tid % 36;
            int glong = lbase - 2 + jt;
            float t = 0.f;
            if (glong >= 0 && glong < 384) {
#pragma unroll
                for (int a = 0; a < 5; a++) {
                    int vi = it + a + (farside ? 0 : -2);
                    if (vi >= 0 && vi < 6) {
#pragma unroll
                        for (int b2 = 0; b2 < 5; b2++) {
                            float kv = horiz ? sk[i * 25 + a * 5 + b2] : sk[i * 25 + b2 * 5 + a];
                            t += kv * vsh[vi * 40 + jt + b2];
                        }
                    }
                }
            }
            tsh[tid] = t;
        }
        __syncthreads();
        if (tid < 64) {
            int io = tid / 32, jo = tid % 32;
            float s = 0.f;
#pragma unroll
            for (int a = 0; a < 5; a++) {
                int it = io + (farside ? 4 : 2) - a;
                if (it >= 0 && it < 4) {
#pragma unroll
                    for (int b2 = 0; b2 < 5; b2++) {
                        int jt = jo + 4 - b2;
                        float kv = horiz ? sk[i * 25 + a * 5 + b2] : sk[i * 25 + b2 * 5 + a];
                        s += kv * tsh[it * 36 + jt];
                    }
                }
            }
            acc += skw[i] * s;
        }
    }
    if (tid < 64) {
        int io = tid / 32, jo = tid % 32;
        int thin = (farside ? 382 : 0) + io;
        int lng = lbase + jo;
        int gy = horiz ? thin : lng;
        int gx = horiz ? lng : thin;
        out[(size_t)bc * HWs + (size_t)gy * WW + gx] = acc;
    }
}

// -------- fused out = sum_i K_i^T ( kw_i * wreg_i * (K_i v) ), iter-1 reg term --------
// double-buffered tt: one barrier per kernel index
__global__ __launch_bounds__(288)
void ata_k(const float* __restrict__ in, float* __restrict__ out,
           const float* __restrict__ ks, const float* __restrict__ kw,
           const float* __restrict__ wreg)
{
    __shared__ float vt[40 * 40];
    __shared__ float tt[2][36 * 36];
    __shared__ float sk[IRK * 25];
    __shared__ float skw[IRK];
    const int bc = blockIdx.z;
    const float* ip = in + (size_t)bc * HWs;
    const int tid = threadIdx.y * 36 + threadIdx.x;
    for (int k = tid; k < IRK * 25; k += 288) sk[k] = ks[k];
    if (tid < IRK) skw[tid] = kw[tid];
    const int X0 = blockIdx.x * 32, Y0 = blockIdx.y * 32;
    for (int k = tid; k < 40 * 40; k += 288) {
        int sy = k / 40, sx = k % 40;
        int gy = Y0 - 4 + sy, gx = X0 - 4 + sx;
        vt[k] = (gy >= 0 && gy < HH && gx >= 0 && gx < WW) ? ip[gy * WW + gx] : 0.f;
    }
    __syncthreads();
    const int tx = threadIdx.x;
    const int ty = threadIdx.y;
    const int syb = ty * 5;
    float a0 = 0, a1 = 0, a2 = 0, a3 = 0;
    int buf = 0;
    for (int i = 0; i < IRK; i++) {
        float kr[25];
#pragma unroll
        for (int k = 0; k < 25; k++) kr[k] = sk[i * 25 + k];
        const float kwv = skw[i];
        // ---- stage 1: t_i on the 36x36 halo region ----
        float tv0 = 0, tv1 = 0, tv2 = 0, tv3 = 0, tv4 = 0;
#pragma unroll
        for (int v = 0; v < 5; v++) {
#pragma unroll
            for (int rr = 0; rr < 9; rr++) {
                float val = vt[(syb + rr) * 40 + tx + v];
                int u;
                u = rr;     if (u <= 4)            tv0 += val * kr[u * 5 + v];
                u = rr - 1; if (u >= 0 && u <= 4)  tv1 += val * kr[u * 5 + v];
                u = rr - 2; if (u >= 0 && u <= 4)  tv2 += val * kr[u * 5 + v];
                u = rr - 3; if (u >= 0 && u <= 4)  tv3 += val * kr[u * 5 + v];
                u = rr - 4; if (u >= 0)            tv4 += val * kr[u * 5 + v];
            }
        }
        {
            float tvs[5] = {tv0, tv1, tv2, tv3, tv4};
#pragma unroll
            for (int k = 0; k < 5; k++) {
                int sy = syb + k;
                if (sy < 36) {
                    int gy = Y0 - 2 + sy, gx = X0 - 2 + tx;
                    float o = 0.f;
                    if (gy >= 0 && gy < HH && gx >= 0 && gx < WW) {
                        float w = kwv * wreg[((size_t)(bc * IRK + i)) * HWs + (size_t)gy * WW + gx];
                        o = tvs[k] * w;
                    }
                    tt[buf][sy * 36 + tx] = o;
                }
            }
        }
        __syncthreads();
        // ---- stage 2: adjoint into per-thread accumulators ----
        if (tx < 32) {
            const int ry = ty * 4;
#pragma unroll
            for (int v = 0; v < 5; v++) {
                int col = tx + 4 - v;
#pragma unroll
                for (int rr = 0; rr < 8; rr++) {
                    float val = tt[buf][(ry + rr) * 36 + col];
                    int u;
                    u = 4 - rr; if (u >= 0 && u <= 4) a0 += val * kr[u * 5 + v];
                    u = 5 - rr; if (u >= 0 && u <= 4) a1 += val * kr[u * 5 + v];
                    u = 6 - rr; if (u >= 0 && u <= 4) a2 += val * kr[u * 5 + v];
                    u = 7 - rr; if (u >= 0 && u <= 4) a3 += val * kr[u * 5 + v];
                }
            }
        }
        buf ^= 1;
    }
    if (tx < 32) {
        const int ry = ty * 4;
        float accs[4] = {a0, a1, a2, a3};
#pragma unroll
        for (int k2 = 0; k2 < 4; k2++) {
            size_t o = (size_t)bc * HWs + (size_t)(Y0 + ry + k2) * WW + X0 + tx;
            out[o] = accs[k2];
        }
    }
}

// -------- GMM reweighting --------
__global__ __launch_bounds__(256)
void gmm_k(const float* __restrict__ x, const float* __restrict__ rks,
           const float* __restrict__ gw, const float* __restrict__ giv)
{
    __shared__ float tile[36 * 36];
    __shared__ float sk[IRK * 25];
    const int bc = blockIdx.z;
    const float* ip = x + (size_t)bc * HWs;
    const int tid = threadIdx.y * 32 + threadIdx.x;
    for (int k = tid; k < IRK * 25; k += 256) sk[k] = rks[k];
    const int X0 = blockIdx.x * 32, Y0 = blockIdx.y * 32;
    for (int k = tid; k < 36 * 36; k += 256) {
        int sy = k / 36, sx = k % 36;
        int gy = Y0 - 2 + sy, gx = X0 - 2 + sx;
        tile[k] = (gy >= 0 && gy < HH && gx >= 0 && gx < WW) ? ip[gy * WW + gx] : 0.f;
    }
    __syncthreads();
    const int ry = threadIdx.y * 4, tx = threadIdx.x;
    for (int j = 0; j < IRK; j++) {
        float kr[25];
#pragma unroll
        for (int k = 0; k < 25; k++) kr[k] = sk[j * 25 + k];
        float g0 = 0, g1 = 0, g2 = 0, g3 = 0;
#pragma unroll
        for (int v = 0; v < 5; v++) {
#pragma unroll
            for (int rr = 0; rr < 8; rr++) {
                float val = tile[(ry + rr) * 36 + tx + v];
                int u;
                u = rr;     if (u <= 4)           g0 += val * kr[u * 5 + v];
                u = rr - 1; if (u >= 0 && u <= 4) g1 += val * kr[u * 5 + v];
                u = rr - 2; if (u >= 0 && u <= 4) g2 += val * kr[u * 5 + v];
                u = rr - 3; if (u >= 0)           g3 += val * kr[u * 5 + v];
            }
        }
        float iv0 = giv[0 * IRK + j], iv1 = giv[1 * IRK + j], iv2 = giv[2 * IRK + j];
        float c0 = gw[0 * IRK + j] * sqrtf(iv0);
        float c1 = gw[1 * IRK + j] * sqrtf(iv1);
        float c2 = gw[2 * IRK + j] * sqrtf(iv2);
        float gs[4] = {g0, g1, g2, g3};
#pragma unroll
        for (int k2 = 0; k2 < 4; k2++) {
            float gv = gs[k2];
            float p0 = c0 * expf(-0.5f * iv0 * gv * gv);
            float p1 = c1 * expf(-0.5f * iv1 * gv * gv);
            float p2 = c2 * expf(-0.5f * iv2 * gv * gv);
            float num = p0 * iv0 + p1 * iv1 + p2 * iv2;
            float den = p0 + p1 + p2 + 1e-12f;
            d_wreg[((size_t)(bc * IRK + j)) * HWs + (size_t)(Y0 + ry + k2) * WW + X0 + tx] = num / den;
        }
    }
}

// ---------------- CG vector kernels (float4, deterministic) ----------------
__global__ __launch_bounds__(256)
void update_xr_k(float* __restrict__ x) {
    const int b = blockIdx.y;
    const float alpha = d_scal[4 + b];
    size_t i4 = ((size_t)b * NBE) / 4 + (size_t)blockIdx.x * 256 + threadIdx.x;
    float4* x4 = (float4*)x;
    float4* p4 = (float4*)d_p;
    float4* r4 = (float4*)d_r;
    float4* a4 = (float4*)d_Ap;
    float4 xv = x4[i4], pv = p4[i4], rv = r4[i4], av = a4[i4];
    xv.x += alpha * pv.x; xv.y += alpha * pv.y; xv.z += alpha * pv.z; xv.w += alpha * pv.w;
    rv.x -= alpha * av.x; rv.y -= alpha * av.y; rv.z -= alpha * av.z; rv.w -= alpha * av.w;
    x4[i4] = xv; r4[i4] = rv;
    float s = rv.x * rv.x + rv.y * rv.y + rv.z * rv.z + rv.w * rv.w;
    float tot;
    if (lastBlockTotal(threadIdx.x, s, b, blockIdx.x, NP_UPD, &tot)) {
        if (threadIdx.x == 0) {
            float rs = d_scal[b];
            int act = d_scal[12 + b] != 0.f;
            d_scal[8 + b] = act ? tot / fmaxf(rs, 1e-12f) : 0.f;  // beta
            d_scal[b] = act ? tot : rs;                            // rs
        }
    }
}

__global__ __launch_bounds__(256)
void update_p_k() {
    const int b = blockIdx.y;
    const float beta = d_scal[8 + b];
    const int active = d_scal[12 + b] != 0.f;
    if (!active) return;
    size_t i4 = ((size_t)b * NBE) / 4 + (size_t)blockIdx.x * 256 + threadIdx.x;
    float4* p4 = (float4*)d_p;
    float4* r4 = (float4*)d_r;
    float4 pv = p4[i4], rv = r4[i4];
    pv.x = rv.x + beta * pv.x; pv.y = rv.y + beta * pv.y;
    pv.z = rv.z + beta * pv.z; pv.w = rv.w + beta * pv.w;
    p4[i4] = pv;
}

// ---------------- host orchestration ----------------
struct Ptrs {
    float *b, *Ap, *t1, *t2, *wreg, *p, *S;
};

// out = A v; mode_final: 1 = fuse dot+alpha; 2 = fuse residual init + rs
static void Aop(const float* v, float* out, int iter, int mode_final, const float* dv,
                const Ptrs& P, const float* kern,
                const float* dks, const float* dkw,
                const float* rks, const float* rkw)
{
    dim3 gc(6, 12, NBC), bl(32, 8);
    dim3 gb(48, 1, NBC);
    // reg term first (plain writes cover the full image)
    if (iter == 0) {
        conv9_k<<<gc, bl>>>(v, out, P.S + 81);
        border_k<<<gb, 256>>>(v, out, rks, rkw, IRK);
    } else {
        ata_k<<<dim3(12, 12, NBC), dim3(36, 8)>>>(v, out, rks, rkw, P.wreg);
    }
    // data term K^T S_d K v, accumulated by the final corr11 (fused epilogue)
    corr11_k<<<gc, bl>>>(v, P.t1, kern, 0, 0, nullptr);
    conv9_k<<<gc, bl>>>(P.t1, P.t2, P.S);
    border_k<<<gb, 256>>>(P.t1, P.t2, dks, dkw, 8);
    corr11_k<<<gc, bl>>>(P.t2, out, kern, 1, mode_final, dv);
}

extern "C" void kernel_launch(void* const* d_in, const int* in_sizes, int n_in,
                              void* d_out, int out_size)
{
    const float* blurred = (const float*)d_in[0];
    const float* kern    = (const float*)d_in[1];
    const float* dkw     = (const float*)d_in[2];
    const float* dks     = (const float*)d_in[3];
    const float* rkw     = (const float*)d_in[4];
    const float* rks     = (const float*)d_in[5];
    const float* gmmw    = (const float*)d_in[6];
    const float* gmmiv   = (const float*)d_in[7];
    float* x = (float*)d_out;

    Ptrs P;
    cudaGetSymbolAddress((void**)&P.b, d_b);
    cudaGetSymbolAddress((void**)&P.Ap, d_Ap);
    cudaGetSymbolAddress((void**)&P.t1, d_t1);
    cudaGetSymbolAddress((void**)&P.t2, d_t2);
    cudaGetSymbolAddress((void**)&P.wreg, d_wreg);
    cudaGetSymbolAddress((void**)&P.p, d_p);
    cudaGetSymbolAddress((void**)&P.S, d_S);
    void* pcnt;
    cudaGetSymbolAddress(&pcnt, d_cnt);

    const int n_irls = 2, n_cg = 8;
    dim3 gc(6, 12, NBC), bl(32, 8);
    dim3 gb(48, 1, NBC);
    dim3 gu(NP_UPD, BB);

    cudaMemsetAsync(pcnt, 0, 8 * sizeof(int), 0);
    autocorr_k<<<1, 256>>>(dks, dkw, rks, rkw);

    // x = blurred
    cudaMemcpyAsync(x, blurred, (size_t)NTOT * sizeof(float),
                    cudaMemcpyDeviceToDevice, 0);

    // b = K^T S_d blurred (+ exact border); IRLS-invariant since reg_targets == 0
    conv9_k<<<gc, bl>>>(blurred, P.t1, P.S);
    border_k<<<gb, 256>>>(blurred, P.t1, dks, dkw, 8);
    corr11_k<<<gc, bl>>>(P.t1, P.b, kern, 1, 0, nullptr);

    for (int it = 0; it < n_irls; it++) {
        if (it == 1)
            gmm_k<<<dim3(12, 12, NBC), dim3(32, 8)>>>(x, rks, gmmw, gmmiv);

        // residual init (r=b-Ax, p=r, rs) fused into final corr11 of Aop(x)
        Aop(x, P.Ap, it, 2, nullptr, P, kern, dks, dkw, rks, rkw);

        for (int s = 0; s < n_cg; s++) {
            // Aop(p): final corr11 fuses dot(p,Ap) and computes alpha/active
            Aop(P.p, P.Ap, it, 1, P.p, P, kern, dks, dkw, rks, rkw);
            update_xr_k<<<gu, 256>>>(x);       // fuses rs_new reduction + beta
            if (s < n_cg - 1)
                update_p_k<<<gu, 256>>>();
        }
    }
}

// round 8
// speedup vs baseline: 1.9217x; 1.1116x over previous
#include <cuda_runtime.h>
#include <math.h>

#define BB 4
#define CC 3
#define HH 384
#define WW 384
#define HWs (HH*WW)
#define NBC 12
#define NTOT (NBC*HWs)
#define NBE (CC*HWs)
#define IRK 16
#define NP_CORR 216   // corr11 blocks per batch (6*12*3)
#define NP_UPD  432   // update_xr blocks per batch

// ------------ static device scratch ------------
__device__ float d_b[NTOT];
__device__ float d_r[NTOT];
__device__ float d_p[NTOT];
__device__ float d_Ap[NTOT];
__device__ float d_t1[NTOT];
__device__ float d_t2[NTOT];
__device__ float d_wreg[(size_t)IRK * NTOT];
__device__ float d_part[BB * 512];
__device__ float d_scal[16]; // [0..3]=rs [4..7]=alpha [8..11]=beta [12..15]=active
__device__ float d_S[162];   // [0..80]=S_data  [81..161]=S_reg
__device__ int   d_cnt[8];   // per-batch completion counters (self-resetting)

__device__ __forceinline__ float warpRed(float v) {
#pragma unroll
    for (int o = 16; o > 0; o >>= 1) v += __shfl_down_sync(0xffffffffu, v, o);
    return v;
}

// Block-reduce s, store partial, detect last block of batch b, then cooperatively
// reduce all nblk partials. Returns true on ALL 256 threads of the last block;
// *tot then holds the full per-batch sum (identical on all threads).
__device__ __forceinline__ bool lastBlockTotal(int tid, float s, int b, int slot,
                                               int nblk, float* tot) {
    __shared__ float sm[8];
    __shared__ int lastF;
    float w = warpRed(s);
    if ((tid & 31) == 0) sm[tid >> 5] = w;
    __syncthreads();
    if (tid == 0) {
        float v = 0;
#pragma unroll
        for (int i = 0; i < 8; i++) v += sm[i];
        d_part[b * 512 + slot] = v;
        __threadfence();
        int old = atomicAdd(&d_cnt[b], 1);
        lastF = (old == nblk - 1);
        if (lastF) d_cnt[b] = 0;
    }
    __syncthreads();
    if (!lastF) return false;
    float t = 0;
    for (int i = tid; i < nblk; i += 256) t += d_part[b * 512 + i];
    t = warpRed(t);
    __syncthreads();
    if ((tid & 31) == 0) sm[tid >> 5] = t;
    __syncthreads();
    float v = 0;
#pragma unroll
    for (int i = 0; i < 8; i++) v += sm[i];
    *tot = v;
    return true;
}

// ------- build composed 9x9 kernels S(d) = sum_i kw_i sum_e k_i(e) k_i(e+d) -------
__global__ void autocorr_k(const float* __restrict__ dks, const float* __restrict__ dkw,
                           const float* __restrict__ rks, const float* __restrict__ rkw)
{
    int tid = threadIdx.x;
    if (tid < 162) {
        int which = tid / 81, t = tid % 81;
        const float* ks = which ? rks : dks;
        const float* kw = which ? rkw : dkw;
        int I = which ? 16 : 8;
        int dy = t / 9 - 4, dx = t % 9 - 4;
        float s = 0.f;
        for (int i = 0; i < I; i++) {
            float w = kw[i];
            for (int u = 0; u < 5; u++)
                for (int v = 0; v < 5; v++) {
                    int u2 = u + dy, v2 = v + dx;
                    if (u2 >= 0 && u2 < 5 && v2 >= 0 && v2 < 5)
                        s += w * ks[i * 25 + u * 5 + v] * ks[i * 25 + u2 * 5 + v2];
                }
        }
        d_S[which * 81 + t] = s;
    }
}

// ---------------- 11x11 per-batch correlation, SAME, zero pad ----------------
// 64x32 tile, block (32,8). thread tx covers cols tx and tx+32 (conflict-free LDS).
// mode 0: out = acc
// mode 1: out += acc; fused dot(out_new, dv); last block computes alpha/active
// mode 2: Ap = out+acc; rv=b-Ap; r=p=rv; fused rs; last block stores rs
__global__ __launch_bounds__(256)
void corr11_k(const float* __restrict__ in, float* __restrict__ out,
              const float* __restrict__ kern, int flip, int mode,
              const float* __restrict__ dv)
{
    __shared__ float tile[42 * 74];
    __shared__ float sk[121];
    const int bc = blockIdx.z;
    const int bat = bc / CC;
    const float* ip = in + (size_t)bc * HWs;
    const int tid = threadIdx.y * 32 + threadIdx.x;
    if (tid < 121) sk[tid] = kern[bat * 121 + (flip ? 120 - tid : tid)];
    const int X0 = blockIdx.x * 64, Y0 = blockIdx.y * 32;
    for (int k = tid; k < 42 * 74; k += 256) {
        int sy = k / 74, sx = k % 74;
        int gy = Y0 - 5 + sy, gx = X0 - 5 + sx;
        tile[k] = (gy >= 0 && gy < HH && gx >= 0 && gx < WW) ? ip[gy * WW + gx] : 0.f;
    }
    __syncthreads();
    const int ry = threadIdx.y * 4;
    const int tx = threadIdx.x;
    float acc0[4] = {0, 0, 0, 0}, acc1[4] = {0, 0, 0, 0};
#pragma unroll
    for (int a = 0; a < 11; a++) {
        float kc[11];
#pragma unroll
        for (int u = 0; u < 11; u++) kc[u] = sk[u * 11 + a];
#pragma unroll
        for (int rr = 0; rr < 14; rr++) {
            float v0 = tile[(ry + rr) * 74 + tx + a];
            float v1 = tile[(ry + rr) * 74 + tx + 32 + a];
#pragma unroll
            for (int k = 0; k < 4; k++) {
                int u = rr - k;
                if (u >= 0 && u <= 10) {
                    acc0[k] += v0 * kc[u];
                    acc1[k] += v1 * kc[u];
                }
            }
        }
    }
    size_t obase = (size_t)bc * HWs + (size_t)(Y0 + ry) * WW + X0 + tx;
    if (mode == 0) {
#pragma unroll
        for (int k = 0; k < 4; k++) {
            out[obase + (size_t)k * WW] = acc0[k];
            out[obase + (size_t)k * WW + 32] = acc1[k];
        }
        return;
    }
    float s = 0.f;
    if (mode == 1) {
#pragma unroll
        for (int k = 0; k < 4; k++) {
            size_t o = obase + (size_t)k * WW;
            float a0 = out[o] + acc0[k]; out[o] = a0; s += a0 * dv[o];
            size_t o1 = o + 32;
            float a1 = out[o1] + acc1[k]; out[o1] = a1; s += a1 * dv[o1];
        }
    } else {
#pragma unroll
        for (int k = 0; k < 4; k++) {
            size_t o = obase + (size_t)k * WW;
            float a0 = out[o] + acc0[k];
            float rv0 = d_b[o] - a0; d_r[o] = rv0; d_p[o] = rv0; s += rv0 * rv0;
            size_t o1 = o + 32;
            float a1 = out[o1] + acc1[k];
            float rv1 = d_b[o1] - a1; d_r[o1] = rv1; d_p[o1] = rv1; s += rv1 * rv1;
        }
    }
    int slot = (bc % CC) * 72 + blockIdx.y * 6 + blockIdx.x;
    float tot;
    if (lastBlockTotal(tid, s, bat, slot, NP_CORR, &tot)) {
        if (tid == 0) {
            if (mode == 2) {
                d_scal[bat] = tot;                 // rs
            } else {
                float rs = d_scal[bat];
                int act = sqrtf(rs) > 1e-6f;
                d_scal[12 + bat] = act ? 1.f : 0.f;
                d_scal[4 + bat] = act ? rs / fmaxf(tot, 1e-12f) : 0.f;  // alpha
            }
        }
    }
}

// ------- 9x9 composed conv, interior only (dist>=2). 64x32 tile, block (32,8) -------
__global__ __launch_bounds__(256)
void conv9_k(const float* __restrict__ in, float* __restrict__ out,
             const float* __restrict__ S)
{
    __shared__ float tile[40 * 72];
    __shared__ float sk[81];
    const int bc = blockIdx.z;
    const float* ip = in + (size_t)bc * HWs;
    const int tid = threadIdx.y * 32 + threadIdx.x;
    if (tid < 81) sk[tid] = S[tid];
    const int X0 = blockIdx.x * 64, Y0 = blockIdx.y * 32;
    for (int k = tid; k < 40 * 72; k += 256) {
        int sy = k / 72, sx = k % 72;
        int gy = Y0 - 4 + sy, gx = X0 - 4 + sx;
        tile[k] = (gy >= 0 && gy < HH && gx >= 0 && gx < WW) ? ip[gy * WW + gx] : 0.f;
    }
    __syncthreads();
    const int ry = threadIdx.y * 4;
    const int tx = threadIdx.x;
    float acc0[4] = {0, 0, 0, 0}, acc1[4] = {0, 0, 0, 0};
#pragma unroll
    for (int a = 0; a < 9; a++) {
        float kc[9];
#pragma unroll
        for (int u = 0; u < 9; u++) kc[u] = sk[u * 9 + a];
#pragma unroll
        for (int rr = 0; rr < 12; rr++) {
            float v0 = tile[(ry + rr) * 72 + tx + a];
            float v1 = tile[(ry + rr) * 72 + tx + 32 + a];
#pragma unroll
            for (int k = 0; k < 4; k++) {
                int u = rr - k;
                if (u >= 0 && u <= 8) {
                    acc0[k] += v0 * kc[u];
                    acc1[k] += v1 * kc[u];
                }
            }
        }
    }
#pragma unroll
    for (int k = 0; k < 4; k++) {
        int oy = Y0 + ry + k;
        if (oy < 2 || oy >= HH - 2) continue;
        size_t rowo = (size_t)bc * HWs + (size_t)oy * WW;
        int ox0 = X0 + tx, ox1 = ox0 + 32;
        if (ox0 >= 2 && ox0 < WW - 2) out[rowo + ox0] = acc0[k];
        if (ox1 >= 2 && ox1 < WW - 2) out[rowo + ox1] = acc1[k];
    }
}

// ------- exact two-stage sum_i kw_i K_i^T K_i on the 2-pixel border frame -------
__global__ __launch_bounds__(256)
void border_k(const float* __restrict__ in, float* __restrict__ out,
              const float* __restrict__ ks, const float* __restrict__ kw, int I)
{
    __shared__ float vsh[6 * 40];
    __shared__ float tsh[4 * 36];
    __shared__ float sk[IRK * 25];
    __shared__ float skw[IRK];
    const int bc = blockIdx.z;
    const int side = blockIdx.x / 12, seg = blockIdx.x % 12;
    const bool horiz = (side < 2);
    const bool farside = (side & 1);
    const int tid = threadIdx.x;
    for (int k = tid; k < I * 25; k += 256) sk[k] = ks[k];
    if (tid < I) skw[tid] = kw[tid];
    const float* ip = in + (size_t)bc * HWs;
    const int lbase = seg * 32;
    if (tid < 240) {
        int i = tid / 40, j = tid % 40;
        int thin = (farside ? 378 : 0) + i;
        int lng = lbase - 4 + j;
        int gy = horiz ? thin : lng;
        int gx = horiz ? lng : thin;
        vsh[tid] = (gy >= 0 && gy < HH && gx >= 0 && gx < WW) ? ip[gy * WW + gx] : 0.f;
    }
    __syncthreads();
    float acc = 0.f;
    for (int i = 0; i < I; i++) {
        __syncthreads();
        if (tid < 144) {
            int it = tid / 36, jt = tid % 36;
            int glong = lbase - 2 + jt;
            float t = 0.f;
            if (glong >= 0 && glong < 384) {
#pragma unroll
                for (int a = 0; a < 5; a++) {
                    int vi = it + a + (farside ? 0 : -2);
                    if (vi >= 0 && vi < 6) {
#pragma unroll
                        for (int b2 = 0; b2 < 5; b2++) {
                            float kv = horiz ? sk[i * 25 + a * 5 + b2] : sk[i * 25 + b2 * 5 + a];
                            t += kv * vsh[vi * 40 + jt + b2];
                        }
                    }
                }
            }
            tsh[tid] = t;
        }
        __syncthreads();
        if (tid < 64) {
            int io = tid / 32, jo = tid % 32;
            float s = 0.f;
#pragma unroll
            for (int a = 0; a < 5; a++) {
                int it = io + (farside ? 4 : 2) - a;
                if (it >= 0 && it < 4) {
#pragma unroll
                    for (int b2 = 0; b2 < 5; b2++) {
                        int jt = jo + 4 - b2;
                        float kv = horiz ? sk[i * 25 + a * 5 + b2] : sk[i * 25 + b2 * 5 + a];
                        s += kv * tsh[it * 36 + jt];
                    }
                }
            }
            acc += skw[i] * s;
        }
    }
    if (tid < 64) {
        int io = tid / 32, jo = tid % 32;
        int thin = (farside ? 382 : 0) + io;
        int lng = lbase + jo;
        int gy = horiz ? thin : lng;
        int gx = horiz ? lng : thin;
        out[(size_t)bc * HWs + (size_t)gy * WW + gx] = acc;
    }
}

// -------- fused out = sum_i K_i^T ( kw_i * wreg_i * (K_i v) ), iter-1 reg term --------
__global__ __launch_bounds__(288)
void ata_k(const float* __restrict__ in, float* __restrict__ out,
           const float* __restrict__ ks, const float* __restrict__ kw,
           const float* __restrict__ wreg)
{
    __shared__ float vt[40 * 40];
    __shared__ float tt[2][36 * 36];
    __shared__ float sk[IRK * 25];
    __shared__ float skw[IRK];
    const int bc = blockIdx.z;
    const float* ip = in + (size_t)bc * HWs;
    const int tid = threadIdx.y * 36 + threadIdx.x;
    for (int k = tid; k < IRK * 25; k += 288) sk[k] = ks[k];
    if (tid < IRK) skw[tid] = kw[tid];
    const int X0 = blockIdx.x * 32, Y0 = blockIdx.y * 32;
    for (int k = tid; k < 40 * 40; k += 288) {
        int sy = k / 40, sx = k % 40;
        int gy = Y0 - 4 + sy, gx = X0 - 4 + sx;
        vt[k] = (gy >= 0 && gy < HH && gx >= 0 && gx < WW) ? ip[gy * WW + gx] : 0.f;
    }
    __syncthreads();
    const int tx = threadIdx.x;
    const int ty = threadIdx.y;
    const int syb = ty * 5;
    float a0 = 0, a1 = 0, a2 = 0, a3 = 0;
    int buf = 0;
    for (int i = 0; i < IRK; i++) {
        float kr[25];
#pragma unroll
        for (int k = 0; k < 25; k++) kr[k] = sk[i * 25 + k];
        const float kwv = skw[i];
        float tv0 = 0, tv1 = 0, tv2 = 0, tv3 = 0, tv4 = 0;
#pragma unroll
        for (int v = 0; v < 5; v++) {
#pragma unroll
            for (int rr = 0; rr < 9; rr++) {
                float val = vt[(syb + rr) * 40 + tx + v];
                int u;
                u = rr;     if (u <= 4)            tv0 += val * kr[u * 5 + v];
                u = rr - 1; if (u >= 0 && u <= 4)  tv1 += val * kr[u * 5 + v];
                u = rr - 2; if (u >= 0 && u <= 4)  tv2 += val * kr[u * 5 + v];
                u = rr - 3; if (u >= 0 && u <= 4)  tv3 += val * kr[u * 5 + v];
                u = rr - 4; if (u >= 0)            tv4 += val * kr[u * 5 + v];
            }
        }
        {
            float tvs[5] = {tv0, tv1, tv2, tv3, tv4};
#pragma unroll
            for (int k = 0; k < 5; k++) {
                int sy = syb + k;
                if (sy < 36) {
                    int gy = Y0 - 2 + sy, gx = X0 - 2 + tx;
                    float o = 0.f;
                    if (gy >= 0 && gy < HH && gx >= 0 && gx < WW) {
                        float w = kwv * wreg[((size_t)(bc * IRK + i)) * HWs + (size_t)gy * WW + gx];
                        o = tvs[k] * w;
                    }
                    tt[buf][sy * 36 + tx] = o;
                }
            }
        }
        __syncthreads();
        if (tx < 32) {
            const int ry = ty * 4;
#pragma unroll
            for (int v = 0; v < 5; v++) {
                int col = tx + 4 - v;
#pragma unroll
                for (int rr = 0; rr < 8; rr++) {
                    float val = tt[buf][(ry + rr) * 36 + col];
                    int u;
                    u = 4 - rr; if (u >= 0 && u <= 4) a0 += val * kr[u * 5 + v];
                    u = 5 - rr; if (u >= 0 && u <= 4) a1 += val * kr[u * 5 + v];
                    u = 6 - rr; if (u >= 0 && u <= 4) a2 += val * kr[u * 5 + v];
                    u = 7 - rr; if (u >= 0 && u <= 4) a3 += val * kr[u * 5 + v];
                }
            }
        }
        buf ^= 1;
    }
    if (tx < 32) {
        const int ry = ty * 4;
        float accs[4] = {a0, a1, a2, a3};
#pragma unroll
        for (int k2 = 0; k2 < 4; k2++) {
            size_t o = (size_t)bc * HWs + (size_t)(Y0 + ry + k2) * WW + X0 + tx;
            out[o] = accs[k2];
        }
    }
}

// -------- GMM reweighting --------
__global__ __launch_bounds__(256)
void gmm_k(const float* __restrict__ x, const float* __restrict__ rks,
           const float* __restrict__ gw, const float* __restrict__ giv)
{
    __shared__ float tile[36 * 36];
    __shared__ float sk[IRK * 25];
    const int bc = blockIdx.z;
    const float* ip = x + (size_t)bc * HWs;
    const int tid = threadIdx.y * 32 + threadIdx.x;
    for (int k = tid; k < IRK * 25; k += 256) sk[k] = rks[k];
    const int X0 = blockIdx.x * 32, Y0 = blockIdx.y * 32;
    for (int k = tid; k < 36 * 36; k += 256) {
        int sy = k / 36, sx = k % 36;
        int gy = Y0 - 2 + sy, gx = X0 - 2 + sx;
        tile[k] = (gy >= 0 && gy < HH && gx >= 0 && gx < WW) ? ip[gy * WW + gx] : 0.f;
    }
    __syncthreads();
    const int ry = threadIdx.y * 4, tx = threadIdx.x;
    for (int j = 0; j < IRK; j++) {
        float kr[25];
#pragma unroll
        for (int k = 0; k < 25; k++) kr[k] = sk[j * 25 + k];
        float g0 = 0, g1 = 0, g2 = 0, g3 = 0;
#pragma unroll
        for (int v = 0; v < 5; v++) {
#pragma unroll
            for (int rr = 0; rr < 8; rr++) {
                float val = tile[(ry + rr) * 36 + tx + v];
                int u;
                u = rr;     if (u <= 4)           g0 += val * kr[u * 5 + v];
                u = rr - 1; if (u >= 0 && u <= 4) g1 += val * kr[u * 5 + v];
                u = rr - 2; if (u >= 0 && u <= 4) g2 += val * kr[u * 5 + v];
                u = rr - 3; if (u >= 0)           g3 += val * kr[u * 5 + v];
            }
        }
        float iv0 = giv[0 * IRK + j], iv1 = giv[1 * IRK + j], iv2 = giv[2 * IRK + j];
        float c0 = gw[0 * IRK + j] * sqrtf(iv0);
        float c1 = gw[1 * IRK + j] * sqrtf(iv1);
        float c2 = gw[2 * IRK + j] * sqrtf(iv2);
        float gs[4] = {g0, g1, g2, g3};
#pragma unroll
        for (int k2 = 0; k2 < 4; k2++) {
            float gv = gs[k2];
            float p0 = c0 * expf(-0.5f * iv0 * gv * gv);
            float p1 = c1 * expf(-0.5f * iv1 * gv * gv);
            float p2 = c2 * expf(-0.5f * iv2 * gv * gv);
            float num = p0 * iv0 + p1 * iv1 + p2 * iv2;
            float den = p0 + p1 + p2 + 1e-12f;
            d_wreg[((size_t)(bc * IRK + j)) * HWs + (size_t)(Y0 + ry + k2) * WW + X0 + tx] = num / den;
        }
    }
}

// ---------------- CG vector kernels (float4, deterministic) ----------------
__global__ __launch_bounds__(256)
void update_xr_k(float* __restrict__ x) {
    const int b = blockIdx.y;
    const float alpha = d_scal[4 + b];
    size_t i4 = ((size_t)b * NBE) / 4 + (size_t)blockIdx.x * 256 + threadIdx.x;
    float4* x4 = (float4*)x;
    float4* p4 = (float4*)d_p;
    float4* r4 = (float4*)d_r;
    float4* a4 = (float4*)d_Ap;
    float4 xv = x4[i4], pv = p4[i4], rv = r4[i4], av = a4[i4];
    xv.x += alpha * pv.x; xv.y += alpha * pv.y; xv.z += alpha * pv.z; xv.w += alpha * pv.w;
    rv.x -= alpha * av.x; rv.y -= alpha * av.y; rv.z -= alpha * av.z; rv.w -= alpha * av.w;
    x4[i4] = xv; r4[i4] = rv;
    float s = rv.x * rv.x + rv.y * rv.y + rv.z * rv.z + rv.w * rv.w;
    float tot;
    if (lastBlockTotal(threadIdx.x, s, b, blockIdx.x, NP_UPD, &tot)) {
        if (threadIdx.x == 0) {
            float rs = d_scal[b];
            int act = d_scal[12 + b] != 0.f;
            d_scal[8 + b] = act ? tot / fmaxf(rs, 1e-12f) : 0.f;  // beta
            d_scal[b] = act ? tot : rs;                            // rs
        }
    }
}

__global__ __launch_bounds__(256)
void update_p_k() {
    const int b = blockIdx.y;
    const float beta = d_scal[8 + b];
    const int active = d_scal[12 + b] != 0.f;
    if (!active) return;
    size_t i4 = ((size_t)b * NBE) / 4 + (size_t)blockIdx.x * 256 + threadIdx.x;
    float4* p4 = (float4*)d_p;
    float4* r4 = (float4*)d_r;
    float4 pv = p4[i4], rv = r4[i4];
    pv.x = rv.x + beta * pv.x; pv.y = rv.y + beta * pv.y;
    pv.z = rv.z + beta * pv.z; pv.w = rv.w + beta * pv.w;
    p4[i4] = pv;
}

// ---------------- host orchestration ----------------
struct Ptrs {
    float *b, *Ap, *t1, *t2, *wreg, *p, *S;
};

extern "C" void kernel_launch(void* const* d_in, const int* in_sizes, int n_in,
                              void* d_out, int out_size)
{
    const float* blurred = (const float*)d_in[0];
    const float* kern    = (const float*)d_in[1];
    const float* dkw     = (const float*)d_in[2];
    const float* dks     = (const float*)d_in[3];
    const float* rkw     = (const float*)d_in[4];
    const float* rks     = (const float*)d_in[5];
    const float* gmmw    = (const float*)d_in[6];
    const float* gmmiv   = (const float*)d_in[7];
    float* x = (float*)d_out;

    Ptrs P;
    cudaGetSymbolAddress((void**)&P.b, d_b);
    cudaGetSymbolAddress((void**)&P.Ap, d_Ap);
    cudaGetSymbolAddress((void**)&P.t1, d_t1);
    cudaGetSymbolAddress((void**)&P.t2, d_t2);
    cudaGetSymbolAddress((void**)&P.wreg, d_wreg);
    cudaGetSymbolAddress((void**)&P.p, d_p);
    cudaGetSymbolAddress((void**)&P.S, d_S);
    void* pcnt;
    cudaGetSymbolAddress(&pcnt, d_cnt);

    const int n_irls = 2, n_cg = 8;
    dim3 gc(6, 12, NBC), bl(32, 8);
    dim3 gb(48, 1, NBC);
    dim3 ga(12, 12, NBC), ba(36, 8);
    dim3 gu(NP_UPD, BB);

    // side stream + events for concurrency (created fresh each call; this host
    // code only runs at correctness + capture time, never during timed replays)
    cudaStream_t s1;
    cudaStreamCreateWithFlags(&s1, cudaStreamNonBlocking);
    cudaEvent_t e0, eA, eB;
    cudaEventCreateWithFlags(&e0, cudaEventDisableTiming);
    cudaEventCreateWithFlags(&eA, cudaEventDisableTiming);
    cudaEventCreateWithFlags(&eB, cudaEventDisableTiming);

    cudaMemsetAsync(pcnt, 0, 8 * sizeof(int), 0);
    autocorr_k<<<1, 256, 0, 0>>>(dks, dkw, rks, rkw);

    // fork: x = blurred on side stream, b-precompute on main
    cudaEventRecord(e0, 0);
    cudaStreamWaitEvent(s1, e0, 0);
    cudaMemcpyAsync(x, blurred, (size_t)NTOT * sizeof(float),
                    cudaMemcpyDeviceToDevice, s1);
    conv9_k<<<gc, bl, 0, 0>>>(blurred, P.t1, P.S);
    border_k<<<gb, 256, 0, 0>>>(blurred, P.t1, dks, dkw, 8);
    corr11_k<<<gc, bl, 0, 0>>>(P.t1, P.b, kern, 1, 0, nullptr);
    cudaEventRecord(eB, s1);
    cudaStreamWaitEvent(0, eB, 0);

    // Aop with the reg term on the side stream; mode_final 1 = fuse dot+alpha,
    // 2 = fuse residual init + rs
    auto AopL = [&](const float* v, int iter, int mode_final, const float* dv) {
        cudaEventRecord(e0, 0);
        cudaStreamWaitEvent(s1, e0, 0);
        // side: full reg term writes Ap everywhere
        if (iter == 0) {
            conv9_k<<<gc, bl, 0, s1>>>(v, P.Ap, P.S + 81);
            border_k<<<gb, 256, 0, s1>>>(v, P.Ap, rks, rkw, IRK);
        } else {
            ata_k<<<ga, ba, 0, s1>>>(v, P.Ap, rks, rkw, P.wreg);
        }
        // main: data chain
        corr11_k<<<gc, bl, 0, 0>>>(v, P.t1, kern, 0, 0, nullptr);
        cudaEventRecord(eA, 0);
        conv9_k<<<gc, bl, 0, 0>>>(P.t1, P.t2, P.S);
        // side: data border concurrent with interior conv9
        cudaStreamWaitEvent(s1, eA, 0);
        border_k<<<gb, 256, 0, s1>>>(P.t1, P.t2, dks, dkw, 8);
        cudaEventRecord(eB, s1);
        // join, then final flipped corr11 accumulates data term into Ap
        cudaStreamWaitEvent(0, eB, 0);
        corr11_k<<<gc, bl, 0, 0>>>(P.t2, P.Ap, kern, 1, mode_final, dv);
    };

    for (int it = 0; it < n_irls; it++) {
        if (it == 1)
            gmm_k<<<dim3(12, 12, NBC), dim3(32, 8), 0, 0>>>(x, rks, gmmw, gmmiv);

        // residual init (r=b-Ax, p=r, rs) fused into final corr11 of Aop(x)
        AopL(x, it, 2, nullptr);

        for (int s = 0; s < n_cg; s++) {
            AopL(P.p, it, 1, P.p);          // fused dot(p,Ap) + alpha/active
            update_xr_k<<<gu, 256, 0, 0>>>(x);  // fused rs_new + beta
            if (s < n_cg - 1)
                update_p_k<<<gu, 256, 0, 0>>>();
        }
    }

    cudaEventDestroy(e0);
    cudaEventDestroy(eA);
    cudaEventDestroy(eB);
    cudaStreamDestroy(s1);
}